// round 10
// baseline (speedup 1.0000x reference)
#include <cuda_runtime.h>
#include <cuda_fp16.h>
#include <cstdint>

// HMMA flash-attention, FA2-style: warps partition KV; S->P stays in
// registers (C-fragment == A-fragment identity); softmax warp-local;
// single end-of-kernel merge. 3-term fp16 split S / 2-term AV.
// Exact JAX threefry dropout, masks precomputed per tile into a bitmask.
// B=4, Q=4096, NKV=4096, H=128, scale=+sqrt(128) folded into Q.
// 256 CTAs x 256 threads; warp w: wr=w>>1 (16 q-rows), wc=w&1 (32-col KV half).

#define TB  256
#define BQ  64
#define BKV 64
#define HD  128
#define NQ  4096
#define NKV 4096
#define NT  (NKV/BKV)

// smem: rows of 256B (128 halves), swizzled
#define SM_QH  0u
#define SM_QL  16384u
#define SM_KH  32768u
#define SM_KL  49152u
#define SM_VH  65536u
#define SM_VL  81920u
#define SM_TOT 98304u
// end-of-kernel merge overlays (reuse K region + start of VH)
#define SM_OBUF 32768u   // 64 x 128 f32 = 32 KB
#define SM_ML   65536u   // 64 x float2

__device__ __forceinline__ uint32_t adr256(uint32_t base, int row, int colB) {
  uint32_t ch = ((uint32_t)colB >> 4) ^ ((uint32_t)row & 7u);
  return base + (uint32_t)row * 256u + ch * 16u + ((uint32_t)colB & 15u);
}
__device__ __forceinline__ uint32_t tadrA(uint32_t base, int r0, int c0, int lane) {
  int rr = r0 + (lane & 7) + ((lane >> 3) & 1) * 8;
  int cB = (c0 + ((lane >> 4) << 3)) * 2;
  return adr256(base, rr, cB);
}
__device__ __forceinline__ uint32_t tadrVT(uint32_t base, int n0, int k0, int lane) {
  int rr = k0 + (lane & 7) + (((lane >> 4) & 1) << 3);
  int cB = (n0 + (((lane >> 3) & 1) << 3)) * 2;
  return adr256(base, rr, cB);
}
__device__ __forceinline__ void ldsm4(uint32_t* r, uint32_t a) {
  asm volatile("ldmatrix.sync.aligned.m8n8.x4.shared.b16 {%0,%1,%2,%3},[%4];"
               : "=r"(r[0]), "=r"(r[1]), "=r"(r[2]), "=r"(r[3]) : "r"(a));
}
__device__ __forceinline__ void ldsm4t(uint32_t* r, uint32_t a) {
  asm volatile("ldmatrix.sync.aligned.m8n8.x4.trans.shared.b16 {%0,%1,%2,%3},[%4];"
               : "=r"(r[0]), "=r"(r[1]), "=r"(r[2]), "=r"(r[3]) : "r"(a));
}
__device__ __forceinline__ void mma_(float* d, const uint32_t* a, uint32_t b0, uint32_t b1) {
  asm volatile(
    "mma.sync.aligned.m16n8k16.row.col.f32.f16.f16.f32 "
    "{%0,%1,%2,%3},{%4,%5,%6,%7},{%8,%9},{%0,%1,%2,%3};"
    : "+f"(d[0]), "+f"(d[1]), "+f"(d[2]), "+f"(d[3])
    : "r"(a[0]), "r"(a[1]), "r"(a[2]), "r"(a[3]), "r"(b0), "r"(b1));
}
__device__ __forceinline__ void sts64(uint32_t a, uint32_t x, uint32_t y) {
  asm volatile("st.shared.v2.b32 [%0],{%1,%2};" :: "r"(a), "r"(x), "r"(y));
}
__device__ __forceinline__ void splith(float a, float b, uint32_t& hi, uint32_t& lo) {
  __half2 h = __floats2half2_rn(a, b);
  float2 hf = __half22float2(h);
  __half2 l = __floats2half2_rn(a - hf.x, b - hf.y);
  hi = *reinterpret_cast<uint32_t*>(&h);
  lo = *reinterpret_cast<uint32_t*>(&l);
}
__device__ __forceinline__ uint32_t packh(float a, float b) {
  __half2 h = __floats2half2_rn(a, b);
  return *reinterpret_cast<uint32_t*>(&h);
}

// JAX threefry2x32-20, key (0,42), partitionable: counter (0,i), bits=x0^x1
__device__ __forceinline__ unsigned keep_mask(unsigned idx) {
  const unsigned ks1 = 42u, ks2 = 0x1BD11BDAu ^ 42u;
  unsigned x0 = 0u, x1 = idx + ks1;
#define TFR(r) { x0 += x1; x1 = __funnelshift_l(x1, x1, (r)); x1 ^= x0; }
  TFR(13) TFR(15) TFR(26) TFR(6)
  x0 += ks1; x1 += ks2 + 1u;
  TFR(17) TFR(29) TFR(16) TFR(24)
  x0 += ks2; x1 += 2u;
  TFR(13) TFR(15) TFR(26) TFR(6)
  x1 += ks1 + 3u;
  TFR(17) TFR(29) TFR(16) TFR(24)
  x0 += ks1; x1 += ks2 + 4u;
  TFR(13) TFR(15) TFR(26) TFR(6)
  x0 += ks2; x1 += 5u;
#undef TFR
  return (((x0 ^ x1) >> 9) < 7549747u) ? 1u : 0u;
}

__global__ void __launch_bounds__(TB, 2)
Model_56358560858161_kernel(const float* __restrict__ Qg, const float* __restrict__ Kg,
                            const float* __restrict__ Vg, float* __restrict__ Og)
{
  extern __shared__ __align__(1024) char smem[];
  const uint32_t sb = (uint32_t)__cvta_generic_to_shared(smem);

  const int tid  = threadIdx.x;
  const int lane = tid & 31, w = tid >> 5;
  const int wr = w >> 1, wc = w & 1;       // 4 row-groups x 2 kv-halves
  const int b  = blockIdx.x >> 6;
  const int q0 = (blockIdx.x & 63) * BQ;

  const float* Qb = Qg + (size_t)b * NQ * HD;
  const float* Kb = Kg + (size_t)b * NKV * HD;
  const float* Vb = Vg + (size_t)b * NKV * HD;
  const unsigned gbase = (unsigned)(b * NQ + q0);

  // ---- Q -> Qh/Ql f16 (scaled), once ---------------------------------------
  {
    const float SC = 11.3137084989847603904f;
    #pragma unroll
    for (int it = 0; it < 8; ++it) {
      int c = tid + it * TB;
      int row = c >> 5, cq = c & 31;
      float4 v = *reinterpret_cast<const float4*>(Qb + (size_t)(q0 + row) * HD + cq * 4);
      uint32_t h0, l0, h1, l1;
      splith(v.x * SC, v.y * SC, h0, l0);
      splith(v.z * SC, v.w * SC, h1, l1);
      sts64(adr256(sb + SM_QH, row, cq * 8), h0, h1);
      sts64(adr256(sb + SM_QL, row, cq * 8), l0, l1);
    }
  }

  float m_[2], l_[2], OA[16][4];
  m_[0] = m_[1] = -1e30f; l_[0] = l_[1] = 0.f;
  #pragma unroll
  for (int nt = 0; nt < 16; ++nt)
    #pragma unroll
    for (int e = 0; e < 4; ++e) OA[nt][e] = 0.f;

  for (int jt = 0; jt < NT; ++jt) {
    const int j0 = jt * BKV;
    __syncthreads();   // all warps done reading prev K/V smem

    // ---- K,V -> split halves (coalesced LDG.128, swizzled STS.64) ---------
    #pragma unroll
    for (int it = 0; it < 8; ++it) {
      int c = tid + it * TB;
      int row = c >> 5, cq = c & 31;
      float4 v = *reinterpret_cast<const float4*>(Kb + (size_t)(j0 + row) * HD + cq * 4);
      uint32_t h0, l0, h1, l1;
      splith(v.x, v.y, h0, l0);
      splith(v.z, v.w, h1, l1);
      sts64(adr256(sb + SM_KH, row, cq * 8), h0, h1);
      sts64(adr256(sb + SM_KL, row, cq * 8), l0, l1);
    }
    #pragma unroll
    for (int it = 0; it < 8; ++it) {
      int c = tid + it * TB;
      int row = c >> 5, cq = c & 31;
      float4 v = *reinterpret_cast<const float4*>(Vb + (size_t)(j0 + row) * HD + cq * 4);
      uint32_t h0, l0, h1, l1;
      splith(v.x, v.y, h0, l0);
      splith(v.z, v.w, h1, l1);
      sts64(adr256(sb + SM_VH, row, cq * 8), h0, h1);
      sts64(adr256(sb + SM_VL, row, cq * 8), l0, l1);
    }
    __syncthreads();

    // ---- dropout bitmask (index-only; overlaps with MMAs below) -----------
    uint32_t km = 0;
    {
      unsigned rb = (gbase + (unsigned)(16 * wr + (lane >> 2))) * (unsigned)NKV
                  + (unsigned)(j0 + 32 * wc + 2 * (lane & 3));
      #pragma unroll
      for (int h2 = 0; h2 < 2; ++h2)
        #pragma unroll
        for (int nt = 0; nt < 4; ++nt) {
          unsigned ib = rb + (unsigned)(h2 * 8 * NKV + 8 * nt);
          km |= keep_mask(ib)      << (h2 * 8 + nt * 2);
          km |= keep_mask(ib + 1u) << (h2 * 8 + nt * 2 + 1);
        }
    }

    // ---- S = Q K^T: 16 rows x 32 cols per warp ----------------------------
    float acc[4][4];
    #pragma unroll
    for (int nt = 0; nt < 4; ++nt)
      #pragma unroll
      for (int e = 0; e < 4; ++e) acc[nt][e] = 0.f;

    #pragma unroll
    for (int ks = 0; ks < 8; ++ks) {
      int k0 = ks * 16;
      uint32_t ah[4], al[4], bh0[4], bh1[4], bl0[4], bl1[4];
      ldsm4(ah,  tadrA(sb + SM_QH, 16 * wr,      k0, lane));
      ldsm4(al,  tadrA(sb + SM_QL, 16 * wr,      k0, lane));
      ldsm4(bh0, tadrA(sb + SM_KH, 32 * wc,      k0, lane));
      ldsm4(bh1, tadrA(sb + SM_KH, 32 * wc + 16, k0, lane));
      ldsm4(bl0, tadrA(sb + SM_KL, 32 * wc,      k0, lane));
      ldsm4(bl1, tadrA(sb + SM_KL, 32 * wc + 16, k0, lane));
      mma_(acc[0], ah, bh0[0], bh0[2]); mma_(acc[1], ah, bh0[1], bh0[3]);
      mma_(acc[2], ah, bh1[0], bh1[2]); mma_(acc[3], ah, bh1[1], bh1[3]);
      mma_(acc[0], ah, bl0[0], bl0[2]); mma_(acc[1], ah, bl0[1], bl0[3]);
      mma_(acc[2], ah, bl1[0], bl1[2]); mma_(acc[3], ah, bl1[1], bl1[3]);
      mma_(acc[0], al, bh0[0], bh0[2]); mma_(acc[1], al, bh0[1], bh0[3]);
      mma_(acc[2], al, bh1[0], bh1[2]); mma_(acc[3], al, bh1[1], bh1[3]);
    }

    // ---- warp-local online softmax ----------------------------------------
    float corr[2];
    #pragma unroll
    for (int h2 = 0; h2 < 2; ++h2) {
      float mx = acc[0][2*h2];
      mx = fmaxf(mx, acc[0][2*h2+1]);
      #pragma unroll
      for (int nt = 1; nt < 4; ++nt)
        mx = fmaxf(mx, fmaxf(acc[nt][2*h2], acc[nt][2*h2+1]));
      mx = fmaxf(mx, __shfl_xor_sync(0xffffffffu, mx, 1));
      mx = fmaxf(mx, __shfl_xor_sync(0xffffffffu, mx, 2));
      float mnew = fmaxf(m_[h2], mx);
      corr[h2] = __expf(m_[h2] - mnew);
      float s = 0.f;
      #pragma unroll
      for (int nt = 0; nt < 4; ++nt)
        #pragma unroll
        for (int e = 0; e < 2; ++e) {
          float ex = __expf(acc[nt][2*h2+e] - mnew);
          acc[nt][2*h2+e] = ex;
          s += ex;
        }
      s += __shfl_xor_sync(0xffffffffu, s, 1);
      s += __shfl_xor_sync(0xffffffffu, s, 2);
      l_[h2] = l_[h2] * corr[h2] + s;
      m_[h2] = mnew;
    }

    // ---- dropout-masked P as AV A-fragments (registers only) --------------
    uint32_t ap[2][4];
    #pragma unroll
    for (int s = 0; s < 2; ++s) {
      #pragma unroll
      for (int q2 = 0; q2 < 2; ++q2) {       // q2: which n8 within the k-16 step
        int nt = 2 * s + q2;
        float e0 = (km >> (nt * 2))       & 1u ? acc[nt][0] : 0.f;
        float e1 = (km >> (nt * 2 + 1))   & 1u ? acc[nt][1] : 0.f;
        float e2 = (km >> (8 + nt * 2))   & 1u ? acc[nt][2] : 0.f;
        float e3 = (km >> (8 + nt * 2 + 1)) & 1u ? acc[nt][3] : 0.f;
        ap[s][q2 * 2]     = packh(e0, e1);   // a0 / a2
        ap[s][q2 * 2 + 1] = packh(e2, e3);   // a1 / a3
      }
    }

    // ---- O = O*corr + P V (full HD per warp, kv slice 32wc) ---------------
    #pragma unroll
    for (int nt = 0; nt < 16; ++nt)
      #pragma unroll
      for (int e = 0; e < 4; ++e) OA[nt][e] *= corr[e >> 1];

    #pragma unroll
    for (int s = 0; s < 2; ++s) {
      int kv0 = 32 * wc + 16 * s;
      #pragma unroll
      for (int ng = 0; ng < 8; ++ng) {
        uint32_t vh[4], vl[4];
        ldsm4t(vh, tadrVT(sb + SM_VH, 16 * ng, kv0, lane));
        ldsm4t(vl, tadrVT(sb + SM_VL, 16 * ng, kv0, lane));
        mma_(OA[2*ng],   ap[s], vh[0], vh[2]);
        mma_(OA[2*ng+1], ap[s], vh[1], vh[3]);
        mma_(OA[2*ng],   ap[s], vl[0], vl[2]);
        mma_(OA[2*ng+1], ap[s], vl[1], vl[3]);
      }
    }
  }

  // ---- end-of-kernel merge across the 2 kv-half warps ----------------------
  __syncthreads();   // everyone done with V smem; overlay Obuf/ML
  float*  Obuf = reinterpret_cast<float*>(smem + SM_OBUF);
  float2* ML   = reinterpret_cast<float2*>(smem + SM_ML);

  if (wc == 1) {
    #pragma unroll
    for (int h2 = 0; h2 < 2; ++h2) {
      int row = 16 * wr + (lane >> 2) + 8 * h2;
      if ((lane & 3) == 0) ML[row] = make_float2(m_[h2], l_[h2]);
    }
    #pragma unroll
    for (int nt = 0; nt < 16; ++nt) {
      int col = 8 * nt + 2 * (lane & 3);
      #pragma unroll
      for (int h2 = 0; h2 < 2; ++h2) {
        int row = 16 * wr + (lane >> 2) + 8 * h2;
        *reinterpret_cast<float2*>(&Obuf[row * HD + col]) =
            make_float2(OA[nt][2*h2], OA[nt][2*h2+1]);
      }
    }
  }
  __syncthreads();
  if (wc == 0) {
    float af[2], bf[2], inv[2];
    #pragma unroll
    for (int h2 = 0; h2 < 2; ++h2) {
      int row = 16 * wr + (lane >> 2) + 8 * h2;
      float2 ml = ML[row];
      float mm = fmaxf(m_[h2], ml.x);
      af[h2] = __expf(m_[h2] - mm);
      bf[h2] = __expf(ml.x - mm);
      float lt = l_[h2] * af[h2] + ml.y * bf[h2];
      inv[h2] = 1.0f / (lt * 0.9f);
    }
    #pragma unroll
    for (int nt = 0; nt < 16; ++nt) {
      int col = 8 * nt + 2 * (lane & 3);
      #pragma unroll
      for (int h2 = 0; h2 < 2; ++h2) {
        int row = 16 * wr + (lane >> 2) + 8 * h2;
        float2 ob = *reinterpret_cast<const float2*>(&Obuf[row * HD + col]);
        float2 o;
        o.x = (OA[nt][2*h2]   * af[h2] + ob.x * bf[h2]) * inv[h2];
        o.y = (OA[nt][2*h2+1] * af[h2] + ob.y * bf[h2]) * inv[h2];
        *reinterpret_cast<float2*>(Og + (size_t)(gbase + row) * HD + col) = o;
      }
    }
  }
}

extern "C" void kernel_launch(void* const* d_in, const int* in_sizes, int n_in,
                              void* d_out, int out_size) {
  const float* Q = (const float*)d_in[0];
  const float* K = (const float*)d_in[1];
  const float* V = (const float*)d_in[2];
  float* O = (float*)d_out;
  (void)in_sizes; (void)n_in; (void)out_size;
  cudaFuncSetAttribute(Model_56358560858161_kernel,
                       cudaFuncAttributeMaxDynamicSharedMemorySize, (int)SM_TOT);
  Model_56358560858161_kernel<<<256, TB, SM_TOT>>>(Q, K, V, O);
}

// round 11
// speedup vs baseline: 1.1185x; 1.1185x over previous
#include <cuda_runtime.h>
#include <cuda_fp16.h>
#include <cstdint>

// Round 11: pre-split Q/K/V to fp16 hi/lo in global scratch (one cheap pass),
// main HMMA flash-attention kernel cp.asyncs f16 tiles directly into swizzled
// smem (double-buffered), no per-tile conversion. R8 compute core (4x4 warp
// grid, BQ=128), 3-term split S / 2-term AV, exact JAX threefry dropout with
// per-tile hoisted bitmask.
// B=4, Q=4096, NKV=4096, H=128, scale=+sqrt(128) folded into Q.

#define TB  512
#define BQ  128
#define BKV 64
#define HD  128
#define NQ  4096
#define NKV 4096
#define NT  (NKV/BKV)
#define NW32 (4*4096*64)   // uint32 (half2) count per split tensor

__device__ uint32_t gQh[NW32], gQl[NW32], gKh[NW32], gKl[NW32], gVh[NW32], gVl[NW32];

// smem byte offsets
#define SM_QH  0u
#define SM_QL  32768u
#define SM_BUF 65536u
#define BUFSZ  65536u
#define OF_KH  0u
#define OF_KL  16384u
#define OF_VH  32768u
#define OF_VL  49152u
#define SM_PH  196608u
#define SM_RED 212992u
#define SM_TOT 217088u

// ---- swizzled addressing (16B chunk ^ (row & 7)) ---------------------------
__device__ __forceinline__ uint32_t adr256(uint32_t base, int row, int colB) {
  uint32_t ch = ((uint32_t)colB >> 4) ^ ((uint32_t)row & 7u);
  return base + (uint32_t)row * 256u + ch * 16u + ((uint32_t)colB & 15u);
}
__device__ __forceinline__ uint32_t adr128(uint32_t base, int row, int colB) {
  uint32_t ch = ((uint32_t)colB >> 4) ^ ((uint32_t)row & 7u);
  return base + (uint32_t)row * 128u + ch * 16u + ((uint32_t)colB & 15u);
}
__device__ __forceinline__ uint32_t tadrA(uint32_t base, int r0, int c0, int lane) {
  int rr = r0 + (lane & 7) + ((lane >> 3) & 1) * 8;
  int cB = (c0 + ((lane >> 4) << 3)) * 2;
  return adr256(base, rr, cB);
}
__device__ __forceinline__ uint32_t tadrP(uint32_t base, int r0, int c0, int lane) {
  int rr = r0 + (lane & 7) + ((lane >> 3) & 1) * 8;
  int cB = (c0 + ((lane >> 4) << 3)) * 2;
  return adr128(base, rr, cB);
}
__device__ __forceinline__ uint32_t tadrVT(uint32_t base, int n0, int k0, int lane) {
  int rr = k0 + (lane & 7) + (((lane >> 4) & 1) << 3);
  int cB = (n0 + (((lane >> 3) & 1) << 3)) * 2;
  return adr256(base, rr, cB);
}
__device__ __forceinline__ void ldsm4(uint32_t* r, uint32_t a) {
  asm volatile("ldmatrix.sync.aligned.m8n8.x4.shared.b16 {%0,%1,%2,%3},[%4];"
               : "=r"(r[0]), "=r"(r[1]), "=r"(r[2]), "=r"(r[3]) : "r"(a));
}
__device__ __forceinline__ void ldsm4t(uint32_t* r, uint32_t a) {
  asm volatile("ldmatrix.sync.aligned.m8n8.x4.trans.shared.b16 {%0,%1,%2,%3},[%4];"
               : "=r"(r[0]), "=r"(r[1]), "=r"(r[2]), "=r"(r[3]) : "r"(a));
}
__device__ __forceinline__ void mma_(float* d, const uint32_t* a, uint32_t b0, uint32_t b1) {
  asm volatile(
    "mma.sync.aligned.m16n8k16.row.col.f32.f16.f16.f32 "
    "{%0,%1,%2,%3},{%4,%5,%6,%7},{%8,%9},{%0,%1,%2,%3};"
    : "+f"(d[0]), "+f"(d[1]), "+f"(d[2]), "+f"(d[3])
    : "r"(a[0]), "r"(a[1]), "r"(a[2]), "r"(a[3]), "r"(b0), "r"(b1));
}
__device__ __forceinline__ void sts32(uint32_t a, uint32_t x) {
  asm volatile("st.shared.b32 [%0],%1;" :: "r"(a), "r"(x));
}
__device__ __forceinline__ void cpa16(uint32_t d, const uint32_t* s) {
  asm volatile("cp.async.cg.shared.global [%0],[%1],16;" :: "r"(d), "l"(s));
}
__device__ __forceinline__ void cpa_commit() { asm volatile("cp.async.commit_group;"); }
__device__ __forceinline__ void cpa_wait1()  { asm volatile("cp.async.wait_group 1;"); }

__device__ __forceinline__ void splith(float a, float b, uint32_t& hi, uint32_t& lo) {
  __half2 h = __floats2half2_rn(a, b);
  float2 hf = __half22float2(h);
  __half2 l = __floats2half2_rn(a - hf.x, b - hf.y);
  hi = *reinterpret_cast<uint32_t*>(&h);
  lo = *reinterpret_cast<uint32_t*>(&l);
}
__device__ __forceinline__ uint32_t packh(float a, float b) {
  __half2 h = __floats2half2_rn(a, b);
  return *reinterpret_cast<uint32_t*>(&h);
}

// JAX threefry2x32-20, key (0,42), partitionable: counter (0,i), bits=x0^x1
__device__ __forceinline__ unsigned keep_mask(unsigned idx) {
  const unsigned ks1 = 42u, ks2 = 0x1BD11BDAu ^ 42u;
  unsigned x0 = 0u, x1 = idx + ks1;
#define TFR(r) { x0 += x1; x1 = __funnelshift_l(x1, x1, (r)); x1 ^= x0; }
  TFR(13) TFR(15) TFR(26) TFR(6)
  x0 += ks1; x1 += ks2 + 1u;
  TFR(17) TFR(29) TFR(16) TFR(24)
  x0 += ks2; x1 += 2u;
  TFR(13) TFR(15) TFR(26) TFR(6)
  x1 += ks1 + 3u;
  TFR(17) TFR(29) TFR(16) TFR(24)
  x0 += ks1; x1 += ks2 + 4u;
  TFR(13) TFR(15) TFR(26) TFR(6)
  x0 += ks2; x1 += 5u;
#undef TFR
  return (((x0 ^ x1) >> 9) < 7549747u) ? 1u : 0u;
}

// ---- pre-split pass: fp32 -> f16 hi/lo (Q scaled by sqrt(128)) -------------
__global__ void __launch_bounds__(512)
presplit_kernel(const float* __restrict__ Q, const float* __restrict__ K,
                const float* __restrict__ V) {
  int i = blockIdx.x * 512 + threadIdx.x;    // float4 index, 0..524287
  const float SC = 11.3137084989847603904f;
  uint32_t h0, l0, h1, l1;
  float4 q = reinterpret_cast<const float4*>(Q)[i];
  splith(q.x * SC, q.y * SC, h0, l0);
  splith(q.z * SC, q.w * SC, h1, l1);
  gQh[2*i] = h0; gQh[2*i+1] = h1; gQl[2*i] = l0; gQl[2*i+1] = l1;
  float4 k = reinterpret_cast<const float4*>(K)[i];
  splith(k.x, k.y, h0, l0);
  splith(k.z, k.w, h1, l1);
  gKh[2*i] = h0; gKh[2*i+1] = h1; gKl[2*i] = l0; gKl[2*i+1] = l1;
  float4 v = reinterpret_cast<const float4*>(V)[i];
  splith(v.x, v.y, h0, l0);
  splith(v.z, v.w, h1, l1);
  gVh[2*i] = h0; gVh[2*i+1] = h1; gVl[2*i] = l0; gVl[2*i+1] = l1;
}

// ---- helper: issue one KV tile's cp.asyncs into a buffer -------------------
__device__ __forceinline__ void issue_tile(uint32_t bb, unsigned src, int tid) {
  #pragma unroll
  for (int it = 0; it < 2; ++it) {
    int c = tid + it * TB;                  // 0..1023
    int row = c >> 4, ch = c & 15;
    unsigned o = src + (unsigned)(row * 64 + ch * 4);
    cpa16(adr256(bb + OF_KH, row, ch * 16), gKh + o);
    cpa16(adr256(bb + OF_KL, row, ch * 16), gKl + o);
    cpa16(adr256(bb + OF_VH, row, ch * 16), gVh + o);
    cpa16(adr256(bb + OF_VL, row, ch * 16), gVl + o);
  }
}

__global__ void __launch_bounds__(TB, 1)
Model_56358560858161_kernel(float* __restrict__ Og) {
  extern __shared__ __align__(1024) char smem[];
  const uint32_t sb = (uint32_t)__cvta_generic_to_shared(smem);
  float2* RED = reinterpret_cast<float2*>(smem + SM_RED);   // [4 wc][128 rows]

  const int tid  = threadIdx.x;
  const int lane = tid & 31, w = tid >> 5;
  const int wr = w & 3, wc = w >> 2;        // 4x4 warp grid
  const int b  = blockIdx.x >> 5;
  const int q0 = (blockIdx.x & 31) * BQ;
  const unsigned gbase  = (unsigned)(b * NQ + q0);
  const unsigned qoff   = gbase * 64u;              // uint32 units
  const unsigned kvbase = (unsigned)(b * NKV) * 64u;

  // ---- prologue: Q (both halves) + KV tile0 -> group0; tile1 -> group1 ----
  #pragma unroll
  for (int it = 0; it < 4; ++it) {
    int c = tid + it * TB;                  // 0..2047
    int row = c >> 4, ch = c & 15;
    unsigned o = qoff + (unsigned)(row * 64 + ch * 4);
    cpa16(adr256(sb + SM_QH, row, ch * 16), gQh + o);
    cpa16(adr256(sb + SM_QL, row, ch * 16), gQl + o);
  }
  issue_tile(sb + SM_BUF, kvbase, tid);
  cpa_commit();
  issue_tile(sb + SM_BUF + BUFSZ, kvbase + (unsigned)BKV * 64u, tid);
  cpa_commit();

  float m_[2][2], l_[2][2], OA[2][4][4];
  #pragma unroll
  for (int mt = 0; mt < 2; ++mt)
    #pragma unroll
    for (int h2 = 0; h2 < 2; ++h2) { m_[mt][h2] = -1e30f; l_[mt][h2] = 0.f; }
  #pragma unroll
  for (int mt = 0; mt < 2; ++mt)
    #pragma unroll
    for (int nt = 0; nt < 4; ++nt)
      #pragma unroll
      for (int e = 0; e < 4; ++e) OA[mt][nt][e] = 0.f;

  for (int jt = 0; jt < NT; ++jt) {
    cpa_wait1();
    __syncthreads();                        // tile jt resident in buf[jt&1]
    const uint32_t bb = sb + SM_BUF + (uint32_t)(jt & 1) * BUFSZ;

    // ---- dropout bitmask (overlaps with S MMAs) ---------------------------
    uint32_t km = 0;
    {
      unsigned rb = (gbase + (unsigned)(32 * wr + (lane >> 2))) * (unsigned)NKV
                  + (unsigned)(jt * BKV + 16 * wc + 2 * (lane & 3));
      #pragma unroll
      for (int mt = 0; mt < 2; ++mt)
        #pragma unroll
        for (int h2 = 0; h2 < 2; ++h2) {
          unsigned ib = rb + (unsigned)((16 * mt + 8 * h2) * NKV);
          int s = mt * 8 + h2 * 4;
          km |= keep_mask(ib)      << s;
          km |= keep_mask(ib + 1u) << (s + 1);
          km |= keep_mask(ib + 8u) << (s + 2);
          km |= keep_mask(ib + 9u) << (s + 3);
        }
    }

    // ---- S = Q K^T: rows 32wr+{0,16}, cols 16wc ---------------------------
    float acc[2][2][4];
    #pragma unroll
    for (int mt = 0; mt < 2; ++mt)
      #pragma unroll
      for (int nt = 0; nt < 2; ++nt)
        #pragma unroll
        for (int e = 0; e < 4; ++e) acc[mt][nt][e] = 0.f;

    #pragma unroll
    for (int ks = 0; ks < 8; ++ks) {
      int k0 = ks * 16;
      uint32_t ah0[4], ah1[4], al0[4], al1[4], bh[4], bl[4];
      ldsm4(ah0, tadrA(sb + SM_QH, 32 * wr,      k0, lane));
      ldsm4(ah1, tadrA(sb + SM_QH, 32 * wr + 16, k0, lane));
      ldsm4(al0, tadrA(sb + SM_QL, 32 * wr,      k0, lane));
      ldsm4(al1, tadrA(sb + SM_QL, 32 * wr + 16, k0, lane));
      ldsm4(bh,  tadrA(bb + OF_KH, 16 * wc,      k0, lane));
      ldsm4(bl,  tadrA(bb + OF_KL, 16 * wc,      k0, lane));
      mma_(acc[0][0], ah0, bh[0], bh[2]); mma_(acc[0][1], ah0, bh[1], bh[3]);
      mma_(acc[1][0], ah1, bh[0], bh[2]); mma_(acc[1][1], ah1, bh[1], bh[3]);
      mma_(acc[0][0], ah0, bl[0], bl[2]); mma_(acc[0][1], ah0, bl[1], bl[3]);
      mma_(acc[1][0], ah1, bl[0], bl[2]); mma_(acc[1][1], ah1, bl[1], bl[3]);
      mma_(acc[0][0], al0, bh[0], bh[2]); mma_(acc[0][1], al0, bh[1], bh[3]);
      mma_(acc[1][0], al1, bh[0], bh[2]); mma_(acc[1][1], al1, bh[1], bh[3]);
    }

    // ---- softmax: warp-local (mw, sw), one sync ---------------------------
    float mw[2][2];
    #pragma unroll
    for (int mt = 0; mt < 2; ++mt)
      #pragma unroll
      for (int h2 = 0; h2 < 2; ++h2) {
        float v0 = acc[mt][0][2*h2], v1 = acc[mt][0][2*h2+1];
        float v2 = acc[mt][1][2*h2], v3 = acc[mt][1][2*h2+1];
        float mx = fmaxf(fmaxf(v0, v1), fmaxf(v2, v3));
        mx = fmaxf(mx, __shfl_xor_sync(0xffffffffu, mx, 1));
        mx = fmaxf(mx, __shfl_xor_sync(0xffffffffu, mx, 2));
        mw[mt][h2] = mx;
        float s = 0.f;
        #pragma unroll
        for (int nt = 0; nt < 2; ++nt)
          #pragma unroll
          for (int e = 0; e < 2; ++e) {
            float ex = __expf(acc[mt][nt][2*h2+e] - mx);
            acc[mt][nt][2*h2+e] = ex;
            s += ex;
          }
        s += __shfl_xor_sync(0xffffffffu, s, 1);
        s += __shfl_xor_sync(0xffffffffu, s, 2);
        if ((lane & 3) == 0) {
          int row = 32 * wr + 16 * mt + 8 * h2 + (lane >> 2);
          RED[wc * 128 + row] = make_float2(mx, s);
        }
      }
    __syncthreads();

    float corr[2][2], f_[2][2];
    #pragma unroll
    for (int mt = 0; mt < 2; ++mt)
      #pragma unroll
      for (int h2 = 0; h2 < 2; ++h2) {
        int row = 32 * wr + 16 * mt + 8 * h2 + (lane >> 2);
        float2 rw[4];
        #pragma unroll
        for (int w2 = 0; w2 < 4; ++w2) rw[w2] = RED[w2 * 128 + row];
        float mnew = m_[mt][h2];
        #pragma unroll
        for (int w2 = 0; w2 < 4; ++w2) mnew = fmaxf(mnew, rw[w2].x);
        float c_ = __expf(m_[mt][h2] - mnew);
        float ls = l_[mt][h2] * c_;
        #pragma unroll
        for (int w2 = 0; w2 < 4; ++w2) ls += rw[w2].y * __expf(rw[w2].x - mnew);
        corr[mt][h2] = c_;
        f_[mt][h2]   = __expf(mw[mt][h2] - mnew);
        l_[mt][h2] = ls;
        m_[mt][h2] = mnew;
      }

    // ---- dropout (bitmask) + P -> smem ------------------------------------
    #pragma unroll
    for (int mt = 0; mt < 2; ++mt)
      #pragma unroll
      for (int h2 = 0; h2 < 2; ++h2) {
        int row = 32 * wr + 16 * mt + 8 * h2 + (lane >> 2);
        float fr = f_[mt][h2];
        int s = mt * 8 + h2 * 4;
        float e0 = (km >> s       & 1u) ? acc[mt][0][2*h2]   * fr : 0.f;
        float e1 = (km >> (s + 1) & 1u) ? acc[mt][0][2*h2+1] * fr : 0.f;
        float e2 = (km >> (s + 2) & 1u) ? acc[mt][1][2*h2]   * fr : 0.f;
        float e3 = (km >> (s + 3) & 1u) ? acc[mt][1][2*h2+1] * fr : 0.f;
        int colB = (16 * wc + 2 * (lane & 3)) * 2;
        sts32(adr128(sb + SM_PH, row, colB),      packh(e0, e1));
        sts32(adr128(sb + SM_PH, row, colB + 16), packh(e2, e3));
      }
    __syncthreads();

    // ---- O = O*corr + P V (V via ldmatrix.trans) --------------------------
    #pragma unroll
    for (int mt = 0; mt < 2; ++mt)
      #pragma unroll
      for (int nt = 0; nt < 4; ++nt)
        #pragma unroll
        for (int e = 0; e < 4; ++e) OA[mt][nt][e] *= corr[mt][e >> 1];

    #pragma unroll
    for (int ks = 0; ks < 4; ++ks) {
      int k0 = ks * 16;
      uint32_t ph0[4], ph1[4], vhA[4], vhB[4], vlA[4], vlB[4];
      ldsm4(ph0,  tadrP(sb + SM_PH, 32 * wr,      k0, lane));
      ldsm4(ph1,  tadrP(sb + SM_PH, 32 * wr + 16, k0, lane));
      ldsm4t(vhA, tadrVT(bb + OF_VH, 32 * wc,      k0, lane));
      ldsm4t(vhB, tadrVT(bb + OF_VH, 32 * wc + 16, k0, lane));
      ldsm4t(vlA, tadrVT(bb + OF_VL, 32 * wc,      k0, lane));
      ldsm4t(vlB, tadrVT(bb + OF_VL, 32 * wc + 16, k0, lane));
      mma_(OA[0][0], ph0, vhA[0], vhA[2]); mma_(OA[0][1], ph0, vhA[1], vhA[3]);
      mma_(OA[0][2], ph0, vhB[0], vhB[2]); mma_(OA[0][3], ph0, vhB[1], vhB[3]);
      mma_(OA[1][0], ph1, vhA[0], vhA[2]); mma_(OA[1][1], ph1, vhA[1], vhA[3]);
      mma_(OA[1][2], ph1, vhB[0], vhB[2]); mma_(OA[1][3], ph1, vhB[1], vhB[3]);
      mma_(OA[0][0], ph0, vlA[0], vlA[2]); mma_(OA[0][1], ph0, vlA[1], vlA[3]);
      mma_(OA[0][2], ph0, vlB[0], vlB[2]); mma_(OA[0][3], ph0, vlB[1], vlB[3]);
      mma_(OA[1][0], ph1, vlA[0], vlA[2]); mma_(OA[1][1], ph1, vlA[1], vlA[3]);
      mma_(OA[1][2], ph1, vlB[0], vlB[2]); mma_(OA[1][3], ph1, vlB[1], vlB[3]);
    }

    __syncthreads();                        // buf[jt&1] reads complete
    if (jt + 2 < NT)
      issue_tile(bb, kvbase + (unsigned)(jt + 2) * BKV * 64u, tid);
    cpa_commit();
  }

  // ---- epilogue ------------------------------------------------------------
  #pragma unroll
  for (int mt = 0; mt < 2; ++mt) {
    float inv0 = 1.0f / (l_[mt][0] * 0.9f);
    float inv1 = 1.0f / (l_[mt][1] * 0.9f);
    #pragma unroll
    for (int nt = 0; nt < 4; ++nt) {
      int col = 32 * wc + 8 * nt + 2 * (lane & 3);
      #pragma unroll
      for (int h2 = 0; h2 < 2; ++h2) {
        int row = 32 * wr + 16 * mt + 8 * h2 + (lane >> 2);
        float inv = h2 ? inv1 : inv0;
        float2 o;
        o.x = OA[mt][nt][2*h2]   * inv;
        o.y = OA[mt][nt][2*h2+1] * inv;
        *reinterpret_cast<float2*>(Og + (size_t)(gbase + row) * HD + col) = o;
      }
    }
  }
}

extern "C" void kernel_launch(void* const* d_in, const int* in_sizes, int n_in,
                              void* d_out, int out_size) {
  const float* Q = (const float*)d_in[0];
  const float* K = (const float*)d_in[1];
  const float* V = (const float*)d_in[2];
  float* O = (float*)d_out;
  (void)in_sizes; (void)n_in; (void)out_size;
  presplit_kernel<<<1024, 512>>>(Q, K, V);
  cudaFuncSetAttribute(Model_56358560858161_kernel,
                       cudaFuncAttributeMaxDynamicSharedMemorySize, (int)SM_TOT);
  Model_56358560858161_kernel<<<128, TB, SM_TOT>>>(O);
}

// round 12
// speedup vs baseline: 1.1368x; 1.0164x over previous
#include <cuda_runtime.h>
#include <cuda_fp16.h>
#include <cstdint>

// Round 12: R11 (pre-split f16 hi/lo in global, cp.async swizzled tiles)
// + barrier-scope narrowing: ONE full __syncthreads per tile; softmax-stats
// and P-visibility barriers become named barriers over the 4 warps of a
// row-group (bar.sync wr+1, 128), letting row-groups run out of phase.
// B=4, Q=4096, NKV=4096, H=128, scale=+sqrt(128) folded into Q.

#define TB  512
#define BQ  128
#define BKV 64
#define HD  128
#define NQ  4096
#define NKV 4096
#define NT  (NKV/BKV)
#define NW32 (4*4096*64)   // uint32 (half2) count per split tensor

__device__ uint32_t gQh[NW32], gQl[NW32], gKh[NW32], gKl[NW32], gVh[NW32], gVl[NW32];

// smem byte offsets
#define SM_QH  0u
#define SM_QL  32768u
#define SM_BUF 65536u
#define BUFSZ  65536u
#define OF_KH  0u
#define OF_KL  16384u
#define OF_VH  32768u
#define OF_VL  49152u
#define SM_PH  196608u
#define SM_RED 212992u
#define SM_TOT 217088u

// ---- swizzled addressing (16B chunk ^ (row & 7)) ---------------------------
__device__ __forceinline__ uint32_t adr256(uint32_t base, int row, int colB) {
  uint32_t ch = ((uint32_t)colB >> 4) ^ ((uint32_t)row & 7u);
  return base + (uint32_t)row * 256u + ch * 16u + ((uint32_t)colB & 15u);
}
__device__ __forceinline__ uint32_t adr128(uint32_t base, int row, int colB) {
  uint32_t ch = ((uint32_t)colB >> 4) ^ ((uint32_t)row & 7u);
  return base + (uint32_t)row * 128u + ch * 16u + ((uint32_t)colB & 15u);
}
__device__ __forceinline__ uint32_t tadrA(uint32_t base, int r0, int c0, int lane) {
  int rr = r0 + (lane & 7) + ((lane >> 3) & 1) * 8;
  int cB = (c0 + ((lane >> 4) << 3)) * 2;
  return adr256(base, rr, cB);
}
__device__ __forceinline__ uint32_t tadrP(uint32_t base, int r0, int c0, int lane) {
  int rr = r0 + (lane & 7) + ((lane >> 3) & 1) * 8;
  int cB = (c0 + ((lane >> 4) << 3)) * 2;
  return adr128(base, rr, cB);
}
__device__ __forceinline__ uint32_t tadrVT(uint32_t base, int n0, int k0, int lane) {
  int rr = k0 + (lane & 7) + (((lane >> 4) & 1) << 3);
  int cB = (n0 + (((lane >> 3) & 1) << 3)) * 2;
  return adr256(base, rr, cB);
}
__device__ __forceinline__ void ldsm4(uint32_t* r, uint32_t a) {
  asm volatile("ldmatrix.sync.aligned.m8n8.x4.shared.b16 {%0,%1,%2,%3},[%4];"
               : "=r"(r[0]), "=r"(r[1]), "=r"(r[2]), "=r"(r[3]) : "r"(a));
}
__device__ __forceinline__ void ldsm4t(uint32_t* r, uint32_t a) {
  asm volatile("ldmatrix.sync.aligned.m8n8.x4.trans.shared.b16 {%0,%1,%2,%3},[%4];"
               : "=r"(r[0]), "=r"(r[1]), "=r"(r[2]), "=r"(r[3]) : "r"(a));
}
__device__ __forceinline__ void mma_(float* d, const uint32_t* a, uint32_t b0, uint32_t b1) {
  asm volatile(
    "mma.sync.aligned.m16n8k16.row.col.f32.f16.f16.f32 "
    "{%0,%1,%2,%3},{%4,%5,%6,%7},{%8,%9},{%0,%1,%2,%3};"
    : "+f"(d[0]), "+f"(d[1]), "+f"(d[2]), "+f"(d[3])
    : "r"(a[0]), "r"(a[1]), "r"(a[2]), "r"(a[3]), "r"(b0), "r"(b1));
}
__device__ __forceinline__ void sts32(uint32_t a, uint32_t x) {
  asm volatile("st.shared.b32 [%0],%1;" :: "r"(a), "r"(x));
}
__device__ __forceinline__ void cpa16(uint32_t d, const uint32_t* s) {
  asm volatile("cp.async.cg.shared.global [%0],[%1],16;" :: "r"(d), "l"(s));
}
__device__ __forceinline__ void cpa_commit() { asm volatile("cp.async.commit_group;"); }
__device__ __forceinline__ void cpa_wait0()  { asm volatile("cp.async.wait_group 0;"); }
__device__ __forceinline__ void barsub(int id) {
  asm volatile("bar.sync %0, 128;" :: "r"(id) : "memory");
}

__device__ __forceinline__ void splith(float a, float b, uint32_t& hi, uint32_t& lo) {
  __half2 h = __floats2half2_rn(a, b);
  float2 hf = __half22float2(h);
  __half2 l = __floats2half2_rn(a - hf.x, b - hf.y);
  hi = *reinterpret_cast<uint32_t*>(&h);
  lo = *reinterpret_cast<uint32_t*>(&l);
}
__device__ __forceinline__ uint32_t packh(float a, float b) {
  __half2 h = __floats2half2_rn(a, b);
  return *reinterpret_cast<uint32_t*>(&h);
}

// JAX threefry2x32-20, key (0,42), partitionable: counter (0,i), bits=x0^x1
__device__ __forceinline__ unsigned keep_mask(unsigned idx) {
  const unsigned ks1 = 42u, ks2 = 0x1BD11BDAu ^ 42u;
  unsigned x0 = 0u, x1 = idx + ks1;
#define TFR(r) { x0 += x1; x1 = __funnelshift_l(x1, x1, (r)); x1 ^= x0; }
  TFR(13) TFR(15) TFR(26) TFR(6)
  x0 += ks1; x1 += ks2 + 1u;
  TFR(17) TFR(29) TFR(16) TFR(24)
  x0 += ks2; x1 += 2u;
  TFR(13) TFR(15) TFR(26) TFR(6)
  x1 += ks1 + 3u;
  TFR(17) TFR(29) TFR(16) TFR(24)
  x0 += ks1; x1 += ks2 + 4u;
  TFR(13) TFR(15) TFR(26) TFR(6)
  x0 += ks2; x1 += 5u;
#undef TFR
  return (((x0 ^ x1) >> 9) < 7549747u) ? 1u : 0u;
}

// ---- pre-split pass: fp32 -> f16 hi/lo (Q scaled by sqrt(128)) -------------
__global__ void __launch_bounds__(512)
presplit_kernel(const float* __restrict__ Q, const float* __restrict__ K,
                const float* __restrict__ V) {
  int i = blockIdx.x * 512 + threadIdx.x;    // float4 index
  const float SC = 11.3137084989847603904f;
  uint32_t h0, l0, h1, l1;
  float4 q = reinterpret_cast<const float4*>(Q)[i];
  splith(q.x * SC, q.y * SC, h0, l0);
  splith(q.z * SC, q.w * SC, h1, l1);
  gQh[2*i] = h0; gQh[2*i+1] = h1; gQl[2*i] = l0; gQl[2*i+1] = l1;
  float4 k = reinterpret_cast<const float4*>(K)[i];
  splith(k.x, k.y, h0, l0);
  splith(k.z, k.w, h1, l1);
  gKh[2*i] = h0; gKh[2*i+1] = h1; gKl[2*i] = l0; gKl[2*i+1] = l1;
  float4 v = reinterpret_cast<const float4*>(V)[i];
  splith(v.x, v.y, h0, l0);
  splith(v.z, v.w, h1, l1);
  gVh[2*i] = h0; gVh[2*i+1] = h1; gVl[2*i] = l0; gVl[2*i+1] = l1;
}

// ---- helper: issue one KV tile's cp.asyncs into a buffer -------------------
__device__ __forceinline__ void issue_tile(uint32_t bb, unsigned src, int tid) {
  #pragma unroll
  for (int it = 0; it < 2; ++it) {
    int c = tid + it * TB;                  // 0..1023
    int row = c >> 4, ch = c & 15;
    unsigned o = src + (unsigned)(row * 64 + ch * 4);
    cpa16(adr256(bb + OF_KH, row, ch * 16), gKh + o);
    cpa16(adr256(bb + OF_KL, row, ch * 16), gKl + o);
    cpa16(adr256(bb + OF_VH, row, ch * 16), gVh + o);
    cpa16(adr256(bb + OF_VL, row, ch * 16), gVl + o);
  }
}

__global__ void __launch_bounds__(TB, 1)
Model_56358560858161_kernel(float* __restrict__ Og) {
  extern __shared__ __align__(1024) char smem[];
  const uint32_t sb = (uint32_t)__cvta_generic_to_shared(smem);
  float2* RED = reinterpret_cast<float2*>(smem + SM_RED);   // [4 wc][128 rows]

  const int tid  = threadIdx.x;
  const int lane = tid & 31, w = tid >> 5;
  const int wr = w & 3, wc = w >> 2;        // 4x4 warp grid
  const int b  = blockIdx.x >> 5;
  const int q0 = (blockIdx.x & 31) * BQ;
  const unsigned gbase  = (unsigned)(b * NQ + q0);
  const unsigned qoff   = gbase * 64u;              // uint32 units
  const unsigned kvbase = (unsigned)(b * NKV) * 64u;

  // ---- prologue: Q (both halves) + KV tile0 -------------------------------
  #pragma unroll
  for (int it = 0; it < 4; ++it) {
    int c = tid + it * TB;                  // 0..2047
    int row = c >> 4, ch = c & 15;
    unsigned o = qoff + (unsigned)(row * 64 + ch * 4);
    cpa16(adr256(sb + SM_QH, row, ch * 16), gQh + o);
    cpa16(adr256(sb + SM_QL, row, ch * 16), gQl + o);
  }
  issue_tile(sb + SM_BUF, kvbase, tid);
  cpa_commit();

  float m_[2][2], l_[2][2], OA[2][4][4];
  #pragma unroll
  for (int mt = 0; mt < 2; ++mt)
    #pragma unroll
    for (int h2 = 0; h2 < 2; ++h2) { m_[mt][h2] = -1e30f; l_[mt][h2] = 0.f; }
  #pragma unroll
  for (int mt = 0; mt < 2; ++mt)
    #pragma unroll
    for (int nt = 0; nt < 4; ++nt)
      #pragma unroll
      for (int e = 0; e < 4; ++e) OA[mt][nt][e] = 0.f;

  for (int jt = 0; jt < NT; ++jt) {
    cpa_wait0();
    __syncthreads();     // tile jt visible; ALL warps done with tile jt-1
    const uint32_t bb = sb + SM_BUF + (uint32_t)(jt & 1) * BUFSZ;

    // issue next tile into the buffer freed by tile jt-1 (safe: full sync)
    if (jt + 1 < NT)
      issue_tile(sb + SM_BUF + (uint32_t)((jt + 1) & 1) * BUFSZ,
                 kvbase + (unsigned)(jt + 1) * BKV * 64u, tid);
    cpa_commit();

    // ---- dropout bitmask (interleaves with S MMAs) ------------------------
    uint32_t km = 0;
    {
      unsigned rb = (gbase + (unsigned)(32 * wr + (lane >> 2))) * (unsigned)NKV
                  + (unsigned)(jt * BKV + 16 * wc + 2 * (lane & 3));
      #pragma unroll
      for (int mt = 0; mt < 2; ++mt)
        #pragma unroll
        for (int h2 = 0; h2 < 2; ++h2) {
          unsigned ib = rb + (unsigned)((16 * mt + 8 * h2) * NKV);
          int s = mt * 8 + h2 * 4;
          km |= keep_mask(ib)      << s;
          km |= keep_mask(ib + 1u) << (s + 1);
          km |= keep_mask(ib + 8u) << (s + 2);
          km |= keep_mask(ib + 9u) << (s + 3);
        }
    }

    // ---- S = Q K^T: rows 32wr+{0,16}, cols 16wc ---------------------------
    float acc[2][2][4];
    #pragma unroll
    for (int mt = 0; mt < 2; ++mt)
      #pragma unroll
      for (int nt = 0; nt < 2; ++nt)
        #pragma unroll
        for (int e = 0; e < 4; ++e) acc[mt][nt][e] = 0.f;

    #pragma unroll
    for (int ks = 0; ks < 8; ++ks) {
      int k0 = ks * 16;
      uint32_t ah0[4], ah1[4], al0[4], al1[4], bh[4], bl[4];
      ldsm4(ah0, tadrA(sb + SM_QH, 32 * wr,      k0, lane));
      ldsm4(ah1, tadrA(sb + SM_QH, 32 * wr + 16, k0, lane));
      ldsm4(al0, tadrA(sb + SM_QL, 32 * wr,      k0, lane));
      ldsm4(al1, tadrA(sb + SM_QL, 32 * wr + 16, k0, lane));
      ldsm4(bh,  tadrA(bb + OF_KH, 16 * wc,      k0, lane));
      ldsm4(bl,  tadrA(bb + OF_KL, 16 * wc,      k0, lane));
      mma_(acc[0][0], ah0, bh[0], bh[2]); mma_(acc[0][1], ah0, bh[1], bh[3]);
      mma_(acc[1][0], ah1, bh[0], bh[2]); mma_(acc[1][1], ah1, bh[1], bh[3]);
      mma_(acc[0][0], ah0, bl[0], bl[2]); mma_(acc[0][1], ah0, bl[1], bl[3]);
      mma_(acc[1][0], ah1, bl[0], bl[2]); mma_(acc[1][1], ah1, bl[1], bl[3]);
      mma_(acc[0][0], al0, bh[0], bh[2]); mma_(acc[0][1], al0, bh[1], bh[3]);
      mma_(acc[1][0], al1, bh[0], bh[2]); mma_(acc[1][1], al1, bh[1], bh[3]);
    }

    // ---- softmax: warp-local (mw, sw); subgroup barrier -------------------
    float mw[2][2];
    #pragma unroll
    for (int mt = 0; mt < 2; ++mt)
      #pragma unroll
      for (int h2 = 0; h2 < 2; ++h2) {
        float v0 = acc[mt][0][2*h2], v1 = acc[mt][0][2*h2+1];
        float v2 = acc[mt][1][2*h2], v3 = acc[mt][1][2*h2+1];
        float mx = fmaxf(fmaxf(v0, v1), fmaxf(v2, v3));
        mx = fmaxf(mx, __shfl_xor_sync(0xffffffffu, mx, 1));
        mx = fmaxf(mx, __shfl_xor_sync(0xffffffffu, mx, 2));
        mw[mt][h2] = mx;
        float s = 0.f;
        #pragma unroll
        for (int nt = 0; nt < 2; ++nt)
          #pragma unroll
          for (int e = 0; e < 2; ++e) {
            float ex = __expf(acc[mt][nt][2*h2+e] - mx);
            acc[mt][nt][2*h2+e] = ex;
            s += ex;
          }
        s += __shfl_xor_sync(0xffffffffu, s, 1);
        s += __shfl_xor_sync(0xffffffffu, s, 2);
        if ((lane & 3) == 0) {
          int row = 32 * wr + 16 * mt + 8 * h2 + (lane >> 2);
          RED[wc * 128 + row] = make_float2(mx, s);
        }
      }
    barsub(1 + wr);      // only the 4 warps sharing this row-group

    float corr[2][2], f_[2][2];
    #pragma unroll
    for (int mt = 0; mt < 2; ++mt)
      #pragma unroll
      for (int h2 = 0; h2 < 2; ++h2) {
        int row = 32 * wr + 16 * mt + 8 * h2 + (lane >> 2);
        float2 rw[4];
        #pragma unroll
        for (int w2 = 0; w2 < 4; ++w2) rw[w2] = RED[w2 * 128 + row];
        float mnew = m_[mt][h2];
        #pragma unroll
        for (int w2 = 0; w2 < 4; ++w2) mnew = fmaxf(mnew, rw[w2].x);
        float c_ = __expf(m_[mt][h2] - mnew);
        float ls = l_[mt][h2] * c_;
        #pragma unroll
        for (int w2 = 0; w2 < 4; ++w2) ls += rw[w2].y * __expf(rw[w2].x - mnew);
        corr[mt][h2] = c_;
        f_[mt][h2]   = __expf(mw[mt][h2] - mnew);
        l_[mt][h2] = ls;
        m_[mt][h2] = mnew;
      }

    // ---- dropout (bitmask) + P -> smem ------------------------------------
    #pragma unroll
    for (int mt = 0; mt < 2; ++mt)
      #pragma unroll
      for (int h2 = 0; h2 < 2; ++h2) {
        int row = 32 * wr + 16 * mt + 8 * h2 + (lane >> 2);
        float fr = f_[mt][h2];
        int s = mt * 8 + h2 * 4;
        float e0 = (km >> s       & 1u) ? acc[mt][0][2*h2]   * fr : 0.f;
        float e1 = (km >> (s + 1) & 1u) ? acc[mt][0][2*h2+1] * fr : 0.f;
        float e2 = (km >> (s + 2) & 1u) ? acc[mt][1][2*h2]   * fr : 0.f;
        float e3 = (km >> (s + 3) & 1u) ? acc[mt][1][2*h2+1] * fr : 0.f;
        int colB = (16 * wc + 2 * (lane & 3)) * 2;
        sts32(adr128(sb + SM_PH, row, colB),      packh(e0, e1));
        sts32(adr128(sb + SM_PH, row, colB + 16), packh(e2, e3));
      }
    barsub(1 + wr);      // P rows of this group visible to its 4 warps

    // ---- O = O*corr + P V (V via ldmatrix.trans) --------------------------
    #pragma unroll
    for (int mt = 0; mt < 2; ++mt)
      #pragma unroll
      for (int nt = 0; nt < 4; ++nt)
        #pragma unroll
        for (int e = 0; e < 4; ++e) OA[mt][nt][e] *= corr[mt][e >> 1];

    #pragma unroll
    for (int ks = 0; ks < 4; ++ks) {
      int k0 = ks * 16;
      uint32_t ph0[4], ph1[4], vhA[4], vhB[4], vlA[4], vlB[4];
      ldsm4(ph0,  tadrP(sb + SM_PH, 32 * wr,      k0, lane));
      ldsm4(ph1,  tadrP(sb + SM_PH, 32 * wr + 16, k0, lane));
      ldsm4t(vhA, tadrVT(bb + OF_VH, 32 * wc,      k0, lane));
      ldsm4t(vhB, tadrVT(bb + OF_VH, 32 * wc + 16, k0, lane));
      ldsm4t(vlA, tadrVT(bb + OF_VL, 32 * wc,      k0, lane));
      ldsm4t(vlB, tadrVT(bb + OF_VL, 32 * wc + 16, k0, lane));
      mma_(OA[0][0], ph0, vhA[0], vhA[2]); mma_(OA[0][1], ph0, vhA[1], vhA[3]);
      mma_(OA[0][2], ph0, vhB[0], vhB[2]); mma_(OA[0][3], ph0, vhB[1], vhB[3]);
      mma_(OA[1][0], ph1, vhA[0], vhA[2]); mma_(OA[1][1], ph1, vhA[1], vhA[3]);
      mma_(OA[1][2], ph1, vhB[0], vhB[2]); mma_(OA[1][3], ph1, vhB[1], vhB[3]);
      mma_(OA[0][0], ph0, vlA[0], vlA[2]); mma_(OA[0][1], ph0, vlA[1], vlA[3]);
      mma_(OA[0][2], ph0, vlB[0], vlB[2]); mma_(OA[0][3], ph0, vlB[1], vlB[3]);
      mma_(OA[1][0], ph1, vlA[0], vlA[2]); mma_(OA[1][1], ph1, vlA[1], vlA[3]);
      mma_(OA[1][2], ph1, vlB[0], vlB[2]); mma_(OA[1][3], ph1, vlB[1], vlB[3]);
    }
  }

  // ---- epilogue ------------------------------------------------------------
  #pragma unroll
  for (int mt = 0; mt < 2; ++mt) {
    float inv0 = 1.0f / (l_[mt][0] * 0.9f);
    float inv1 = 1.0f / (l_[mt][1] * 0.9f);
    #pragma unroll
    for (int nt = 0; nt < 4; ++nt) {
      int col = 32 * wc + 8 * nt + 2 * (lane & 3);
      #pragma unroll
      for (int h2 = 0; h2 < 2; ++h2) {
        int row = 32 * wr + 16 * mt + 8 * h2 + (lane >> 2);
        float inv = h2 ? inv1 : inv0;
        float2 o;
        o.x = OA[mt][nt][2*h2]   * inv;
        o.y = OA[mt][nt][2*h2+1] * inv;
        *reinterpret_cast<float2*>(Og + (size_t)(gbase + row) * HD + col) = o;
      }
    }
  }
}

extern "C" void kernel_launch(void* const* d_in, const int* in_sizes, int n_in,
                              void* d_out, int out_size) {
  const float* Q = (const float*)d_in[0];
  const float* K = (const float*)d_in[1];
  const float* V = (const float*)d_in[2];
  float* O = (float*)d_out;
  (void)in_sizes; (void)n_in; (void)out_size;
  presplit_kernel<<<1024, 512>>>(Q, K, V);
  cudaFuncSetAttribute(Model_56358560858161_kernel,
                       cudaFuncAttributeMaxDynamicSharedMemorySize, (int)SM_TOT);
  Model_56358560858161_kernel<<<128, TB, SM_TOT>>>(O);
}

// round 13
// speedup vs baseline: 1.1753x; 1.0339x over previous
#include <cuda_runtime.h>
#include <cuda_fp16.h>
#include <cstdint>

// Round 13: R12 core (pre-split f16 hi/lo, swizzled cp.async, bitmask threefry,
// named row-group barriers) at BQ=64 / TB=256 / 256 CTAs -> 2 CTAs per SM for
// cross-CTA phase overlap. Single-buffered KV (mask gen + co-CTA hide latency).
// B=4, Q=4096, NKV=4096, H=128, scale=+sqrt(128) folded into Q.

#define TB  256
#define BQ  64
#define BKV 64
#define HD  128
#define NQ  4096
#define NKV 4096
#define NT  (NKV/BKV)
#define NW32 (4*4096*64)   // uint32 (half2) count per split tensor

__device__ uint32_t gQh[NW32], gQl[NW32], gKh[NW32], gKl[NW32], gVh[NW32], gVl[NW32];

// smem byte offsets (per-CTA total 106 KB -> 2 CTAs/SM)
#define SM_QH  0u
#define SM_QL  16384u
#define SM_BUF 32768u
#define OF_KH  0u
#define OF_KL  16384u
#define OF_VH  32768u
#define OF_VL  49152u
#define SM_PH  98304u
#define SM_RED 106496u
#define SM_TOT 108544u

// ---- swizzled addressing (16B chunk ^ (row & 7)) ---------------------------
__device__ __forceinline__ uint32_t adr256(uint32_t base, int row, int colB) {
  uint32_t ch = ((uint32_t)colB >> 4) ^ ((uint32_t)row & 7u);
  return base + (uint32_t)row * 256u + ch * 16u + ((uint32_t)colB & 15u);
}
__device__ __forceinline__ uint32_t adr128(uint32_t base, int row, int colB) {
  uint32_t ch = ((uint32_t)colB >> 4) ^ ((uint32_t)row & 7u);
  return base + (uint32_t)row * 128u + ch * 16u + ((uint32_t)colB & 15u);
}
__device__ __forceinline__ uint32_t tadrA(uint32_t base, int r0, int c0, int lane) {
  int rr = r0 + (lane & 7) + ((lane >> 3) & 1) * 8;
  int cB = (c0 + ((lane >> 4) << 3)) * 2;
  return adr256(base, rr, cB);
}
__device__ __forceinline__ uint32_t tadrP(uint32_t base, int r0, int c0, int lane) {
  int rr = r0 + (lane & 7) + ((lane >> 3) & 1) * 8;
  int cB = (c0 + ((lane >> 4) << 3)) * 2;
  return adr128(base, rr, cB);
}
__device__ __forceinline__ uint32_t tadrVT(uint32_t base, int n0, int k0, int lane) {
  int rr = k0 + (lane & 7) + (((lane >> 4) & 1) << 3);
  int cB = (n0 + (((lane >> 3) & 1) << 3)) * 2;
  return adr256(base, rr, cB);
}
__device__ __forceinline__ void ldsm4(uint32_t* r, uint32_t a) {
  asm volatile("ldmatrix.sync.aligned.m8n8.x4.shared.b16 {%0,%1,%2,%3},[%4];"
               : "=r"(r[0]), "=r"(r[1]), "=r"(r[2]), "=r"(r[3]) : "r"(a));
}
__device__ __forceinline__ void ldsm4t(uint32_t* r, uint32_t a) {
  asm volatile("ldmatrix.sync.aligned.m8n8.x4.trans.shared.b16 {%0,%1,%2,%3},[%4];"
               : "=r"(r[0]), "=r"(r[1]), "=r"(r[2]), "=r"(r[3]) : "r"(a));
}
__device__ __forceinline__ void mma_(float* d, const uint32_t* a, uint32_t b0, uint32_t b1) {
  asm volatile(
    "mma.sync.aligned.m16n8k16.row.col.f32.f16.f16.f32 "
    "{%0,%1,%2,%3},{%4,%5,%6,%7},{%8,%9},{%0,%1,%2,%3};"
    : "+f"(d[0]), "+f"(d[1]), "+f"(d[2]), "+f"(d[3])
    : "r"(a[0]), "r"(a[1]), "r"(a[2]), "r"(a[3]), "r"(b0), "r"(b1));
}
__device__ __forceinline__ void sts32(uint32_t a, uint32_t x) {
  asm volatile("st.shared.b32 [%0],%1;" :: "r"(a), "r"(x));
}
__device__ __forceinline__ void cpa16(uint32_t d, const uint32_t* s) {
  asm volatile("cp.async.cg.shared.global [%0],[%1],16;" :: "r"(d), "l"(s));
}
__device__ __forceinline__ void cpa_commit() { asm volatile("cp.async.commit_group;"); }
__device__ __forceinline__ void cpa_wait0()  { asm volatile("cp.async.wait_group 0;"); }
__device__ __forceinline__ void barsub(int id) {
  asm volatile("bar.sync %0, 128;" :: "r"(id) : "memory");
}

__device__ __forceinline__ void splith(float a, float b, uint32_t& hi, uint32_t& lo) {
  __half2 h = __floats2half2_rn(a, b);
  float2 hf = __half22float2(h);
  __half2 l = __floats2half2_rn(a - hf.x, b - hf.y);
  hi = *reinterpret_cast<uint32_t*>(&h);
  lo = *reinterpret_cast<uint32_t*>(&l);
}
__device__ __forceinline__ uint32_t packh(float a, float b) {
  __half2 h = __floats2half2_rn(a, b);
  return *reinterpret_cast<uint32_t*>(&h);
}

// JAX threefry2x32-20, key (0,42), partitionable: counter (0,i), bits=x0^x1
__device__ __forceinline__ unsigned keep_mask(unsigned idx) {
  const unsigned ks1 = 42u, ks2 = 0x1BD11BDAu ^ 42u;
  unsigned x0 = 0u, x1 = idx + ks1;
#define TFR(r) { x0 += x1; x1 = __funnelshift_l(x1, x1, (r)); x1 ^= x0; }
  TFR(13) TFR(15) TFR(26) TFR(6)
  x0 += ks1; x1 += ks2 + 1u;
  TFR(17) TFR(29) TFR(16) TFR(24)
  x0 += ks2; x1 += 2u;
  TFR(13) TFR(15) TFR(26) TFR(6)
  x1 += ks1 + 3u;
  TFR(17) TFR(29) TFR(16) TFR(24)
  x0 += ks1; x1 += ks2 + 4u;
  TFR(13) TFR(15) TFR(26) TFR(6)
  x0 += ks2; x1 += 5u;
#undef TFR
  return (((x0 ^ x1) >> 9) < 7549747u) ? 1u : 0u;
}

// ---- pre-split pass: fp32 -> f16 hi/lo (Q scaled by sqrt(128)) -------------
__global__ void __launch_bounds__(512)
presplit_kernel(const float* __restrict__ Q, const float* __restrict__ K,
                const float* __restrict__ V) {
  int i = blockIdx.x * 512 + threadIdx.x;    // float4 index
  const float SC = 11.3137084989847603904f;
  uint32_t h0, l0, h1, l1;
  float4 q = reinterpret_cast<const float4*>(Q)[i];
  splith(q.x * SC, q.y * SC, h0, l0);
  splith(q.z * SC, q.w * SC, h1, l1);
  gQh[2*i] = h0; gQh[2*i+1] = h1; gQl[2*i] = l0; gQl[2*i+1] = l1;
  float4 k = reinterpret_cast<const float4*>(K)[i];
  splith(k.x, k.y, h0, l0);
  splith(k.z, k.w, h1, l1);
  gKh[2*i] = h0; gKh[2*i+1] = h1; gKl[2*i] = l0; gKl[2*i+1] = l1;
  float4 v = reinterpret_cast<const float4*>(V)[i];
  splith(v.x, v.y, h0, l0);
  splith(v.z, v.w, h1, l1);
  gVh[2*i] = h0; gVh[2*i+1] = h1; gVl[2*i] = l0; gVl[2*i+1] = l1;
}

// ---- helper: issue one KV tile's cp.asyncs (16 per thread at TB=256) -------
__device__ __forceinline__ void issue_tile(uint32_t bb, unsigned src, int tid) {
  #pragma unroll
  for (int it = 0; it < 4; ++it) {
    int c = tid + it * TB;                  // 0..1023
    int row = c >> 4, ch = c & 15;
    unsigned o = src + (unsigned)(row * 64 + ch * 4);
    cpa16(adr256(bb + OF_KH, row, ch * 16), gKh + o);
    cpa16(adr256(bb + OF_KL, row, ch * 16), gKl + o);
    cpa16(adr256(bb + OF_VH, row, ch * 16), gVh + o);
    cpa16(adr256(bb + OF_VL, row, ch * 16), gVl + o);
  }
}

__global__ void __launch_bounds__(TB, 2)
Model_56358560858161_kernel(float* __restrict__ Og) {
  extern __shared__ __align__(1024) char smem[];
  const uint32_t sb = (uint32_t)__cvta_generic_to_shared(smem);
  float2* RED = reinterpret_cast<float2*>(smem + SM_RED);   // [4 wc][64 rows]

  const int tid  = threadIdx.x;
  const int lane = tid & 31, w = tid >> 5;
  const int wr = w & 1, wc = w >> 1;        // 2 row-groups x 4 col-warps
  const int b  = blockIdx.x >> 6;
  const int q0 = (blockIdx.x & 63) * BQ;
  const unsigned gbase  = (unsigned)(b * NQ + q0);
  const unsigned qoff   = gbase * 64u;              // uint32 units
  const unsigned kvbase = (unsigned)(b * NKV) * 64u;

  // ---- prologue: Q (both halves) ------------------------------------------
  #pragma unroll
  for (int it = 0; it < 4; ++it) {
    int c = tid + it * TB;                  // 0..1023
    int row = c >> 4, ch = c & 15;
    unsigned o = qoff + (unsigned)(row * 64 + ch * 4);
    cpa16(adr256(sb + SM_QH, row, ch * 16), gQh + o);
    cpa16(adr256(sb + SM_QL, row, ch * 16), gQl + o);
  }
  cpa_commit();

  float m_[2][2], l_[2][2], OA[2][4][4];
  #pragma unroll
  for (int mt = 0; mt < 2; ++mt)
    #pragma unroll
    for (int h2 = 0; h2 < 2; ++h2) { m_[mt][h2] = -1e30f; l_[mt][h2] = 0.f; }
  #pragma unroll
  for (int mt = 0; mt < 2; ++mt)
    #pragma unroll
    for (int nt = 0; nt < 4; ++nt)
      #pragma unroll
      for (int e = 0; e < 4; ++e) OA[mt][nt][e] = 0.f;

  for (int jt = 0; jt < NT; ++jt) {
    __syncthreads();      // all warps done with tile jt-1's KV + P smem
    issue_tile(sb + SM_BUF, kvbase + (unsigned)jt * BKV * 64u, tid);
    cpa_commit();

    // ---- dropout bitmask (covers cp.async latency) ------------------------
    uint32_t km = 0;
    {
      unsigned rb = (gbase + (unsigned)(32 * wr + (lane >> 2))) * (unsigned)NKV
                  + (unsigned)(jt * BKV + 16 * wc + 2 * (lane & 3));
      #pragma unroll
      for (int mt = 0; mt < 2; ++mt)
        #pragma unroll
        for (int h2 = 0; h2 < 2; ++h2) {
          unsigned ib = rb + (unsigned)((16 * mt + 8 * h2) * NKV);
          int s = mt * 8 + h2 * 4;
          km |= keep_mask(ib)      << s;
          km |= keep_mask(ib + 1u) << (s + 1);
          km |= keep_mask(ib + 8u) << (s + 2);
          km |= keep_mask(ib + 9u) << (s + 3);
        }
    }

    cpa_wait0();
    __syncthreads();      // tile jt visible
    const uint32_t bb = sb + SM_BUF;

    // ---- S = Q K^T: rows 32wr+{0,16}, cols 16wc ---------------------------
    float acc[2][2][4];
    #pragma unroll
    for (int mt = 0; mt < 2; ++mt)
      #pragma unroll
      for (int nt = 0; nt < 2; ++nt)
        #pragma unroll
        for (int e = 0; e < 4; ++e) acc[mt][nt][e] = 0.f;

    #pragma unroll
    for (int ks = 0; ks < 8; ++ks) {
      int k0 = ks * 16;
      uint32_t ah0[4], ah1[4], al0[4], al1[4], bh[4], bl[4];
      ldsm4(ah0, tadrA(sb + SM_QH, 32 * wr,      k0, lane));
      ldsm4(ah1, tadrA(sb + SM_QH, 32 * wr + 16, k0, lane));
      ldsm4(al0, tadrA(sb + SM_QL, 32 * wr,      k0, lane));
      ldsm4(al1, tadrA(sb + SM_QL, 32 * wr + 16, k0, lane));
      ldsm4(bh,  tadrA(bb + OF_KH, 16 * wc,      k0, lane));
      ldsm4(bl,  tadrA(bb + OF_KL, 16 * wc,      k0, lane));
      mma_(acc[0][0], ah0, bh[0], bh[2]); mma_(acc[0][1], ah0, bh[1], bh[3]);
      mma_(acc[1][0], ah1, bh[0], bh[2]); mma_(acc[1][1], ah1, bh[1], bh[3]);
      mma_(acc[0][0], ah0, bl[0], bl[2]); mma_(acc[0][1], ah0, bl[1], bl[3]);
      mma_(acc[1][0], ah1, bl[0], bl[2]); mma_(acc[1][1], ah1, bl[1], bl[3]);
      mma_(acc[0][0], al0, bh[0], bh[2]); mma_(acc[0][1], al0, bh[1], bh[3]);
      mma_(acc[1][0], al1, bh[0], bh[2]); mma_(acc[1][1], al1, bh[1], bh[3]);
    }

    // ---- softmax: warp-local (mw, sw); row-group barrier ------------------
    float mw[2][2];
    #pragma unroll
    for (int mt = 0; mt < 2; ++mt)
      #pragma unroll
      for (int h2 = 0; h2 < 2; ++h2) {
        float v0 = acc[mt][0][2*h2], v1 = acc[mt][0][2*h2+1];
        float v2 = acc[mt][1][2*h2], v3 = acc[mt][1][2*h2+1];
        float mx = fmaxf(fmaxf(v0, v1), fmaxf(v2, v3));
        mx = fmaxf(mx, __shfl_xor_sync(0xffffffffu, mx, 1));
        mx = fmaxf(mx, __shfl_xor_sync(0xffffffffu, mx, 2));
        mw[mt][h2] = mx;
        float s = 0.f;
        #pragma unroll
        for (int nt = 0; nt < 2; ++nt)
          #pragma unroll
          for (int e = 0; e < 2; ++e) {
            float ex = __expf(acc[mt][nt][2*h2+e] - mx);
            acc[mt][nt][2*h2+e] = ex;
            s += ex;
          }
        s += __shfl_xor_sync(0xffffffffu, s, 1);
        s += __shfl_xor_sync(0xffffffffu, s, 2);
        if ((lane & 3) == 0) {
          int row = 32 * wr + 16 * mt + 8 * h2 + (lane >> 2);
          RED[wc * 64 + row] = make_float2(mx, s);
        }
      }
    barsub(1 + wr);       // 4 warps of this row-group

    float corr[2][2], f_[2][2];
    #pragma unroll
    for (int mt = 0; mt < 2; ++mt)
      #pragma unroll
      for (int h2 = 0; h2 < 2; ++h2) {
        int row = 32 * wr + 16 * mt + 8 * h2 + (lane >> 2);
        float2 rw[4];
        #pragma unroll
        for (int w2 = 0; w2 < 4; ++w2) rw[w2] = RED[w2 * 64 + row];
        float mnew = m_[mt][h2];
        #pragma unroll
        for (int w2 = 0; w2 < 4; ++w2) mnew = fmaxf(mnew, rw[w2].x);
        float c_ = __expf(m_[mt][h2] - mnew);
        float ls = l_[mt][h2] * c_;
        #pragma unroll
        for (int w2 = 0; w2 < 4; ++w2) ls += rw[w2].y * __expf(rw[w2].x - mnew);
        corr[mt][h2] = c_;
        f_[mt][h2]   = __expf(mw[mt][h2] - mnew);
        l_[mt][h2] = ls;
        m_[mt][h2] = mnew;
      }

    // ---- dropout (bitmask) + P -> smem ------------------------------------
    #pragma unroll
    for (int mt = 0; mt < 2; ++mt)
      #pragma unroll
      for (int h2 = 0; h2 < 2; ++h2) {
        int row = 32 * wr + 16 * mt + 8 * h2 + (lane >> 2);
        float fr = f_[mt][h2];
        int s = mt * 8 + h2 * 4;
        float e0 = (km >> s       & 1u) ? acc[mt][0][2*h2]   * fr : 0.f;
        float e1 = (km >> (s + 1) & 1u) ? acc[mt][0][2*h2+1] * fr : 0.f;
        float e2 = (km >> (s + 2) & 1u) ? acc[mt][1][2*h2]   * fr : 0.f;
        float e3 = (km >> (s + 3) & 1u) ? acc[mt][1][2*h2+1] * fr : 0.f;
        int colB = (16 * wc + 2 * (lane & 3)) * 2;
        sts32(adr128(sb + SM_PH, row, colB),      packh(e0, e1));
        sts32(adr128(sb + SM_PH, row, colB + 16), packh(e2, e3));
      }
    barsub(1 + wr);       // P rows of this group visible to its 4 warps

    // ---- O = O*corr + P V (V via ldmatrix.trans) --------------------------
    #pragma unroll
    for (int mt = 0; mt < 2; ++mt)
      #pragma unroll
      for (int nt = 0; nt < 4; ++nt)
        #pragma unroll
        for (int e = 0; e < 4; ++e) OA[mt][nt][e] *= corr[mt][e >> 1];

    #pragma unroll
    for (int ks = 0; ks < 4; ++ks) {
      int k0 = ks * 16;
      uint32_t ph0[4], ph1[4], vhA[4], vhB[4], vlA[4], vlB[4];
      ldsm4(ph0,  tadrP(sb + SM_PH, 32 * wr,      k0, lane));
      ldsm4(ph1,  tadrP(sb + SM_PH, 32 * wr + 16, k0, lane));
      ldsm4t(vhA, tadrVT(bb + OF_VH, 32 * wc,      k0, lane));
      ldsm4t(vhB, tadrVT(bb + OF_VH, 32 * wc + 16, k0, lane));
      ldsm4t(vlA, tadrVT(bb + OF_VL, 32 * wc,      k0, lane));
      ldsm4t(vlB, tadrVT(bb + OF_VL, 32 * wc + 16, k0, lane));
      mma_(OA[0][0], ph0, vhA[0], vhA[2]); mma_(OA[0][1], ph0, vhA[1], vhA[3]);
      mma_(OA[0][2], ph0, vhB[0], vhB[2]); mma_(OA[0][3], ph0, vhB[1], vhB[3]);
      mma_(OA[1][0], ph1, vhA[0], vhA[2]); mma_(OA[1][1], ph1, vhA[1], vhA[3]);
      mma_(OA[1][2], ph1, vhB[0], vhB[2]); mma_(OA[1][3], ph1, vhB[1], vhB[3]);
      mma_(OA[0][0], ph0, vlA[0], vlA[2]); mma_(OA[0][1], ph0, vlA[1], vlA[3]);
      mma_(OA[0][2], ph0, vlB[0], vlB[2]); mma_(OA[0][3], ph0, vlB[1], vlB[3]);
      mma_(OA[1][0], ph1, vlA[0], vlA[2]); mma_(OA[1][1], ph1, vlA[1], vlA[3]);
      mma_(OA[1][2], ph1, vlB[0], vlB[2]); mma_(OA[1][3], ph1, vlB[1], vlB[3]);
    }
  }

  // ---- epilogue ------------------------------------------------------------
  #pragma unroll
  for (int mt = 0; mt < 2; ++mt) {
    float inv0 = 1.0f / (l_[mt][0] * 0.9f);
    float inv1 = 1.0f / (l_[mt][1] * 0.9f);
    #pragma unroll
    for (int nt = 0; nt < 4; ++nt) {
      int col = 32 * wc + 8 * nt + 2 * (lane & 3);
      #pragma unroll
      for (int h2 = 0; h2 < 2; ++h2) {
        int row = 32 * wr + 16 * mt + 8 * h2 + (lane >> 2);
        float inv = h2 ? inv1 : inv0;
        float2 o;
        o.x = OA[mt][nt][2*h2]   * inv;
        o.y = OA[mt][nt][2*h2+1] * inv;
        *reinterpret_cast<float2*>(Og + (size_t)(gbase + row) * HD + col) = o;
      }
    }
  }
}

extern "C" void kernel_launch(void* const* d_in, const int* in_sizes, int n_in,
                              void* d_out, int out_size) {
  const float* Q = (const float*)d_in[0];
  const float* K = (const float*)d_in[1];
  const float* V = (const float*)d_in[2];
  float* O = (float*)d_out;
  (void)in_sizes; (void)n_in; (void)out_size;
  presplit_kernel<<<1024, 512>>>(Q, K, V);
  cudaFuncSetAttribute(Model_56358560858161_kernel,
                       cudaFuncAttributeMaxDynamicSharedMemorySize, (int)SM_TOT);
  Model_56358560858161_kernel<<<256, TB, SM_TOT>>>(O);
}

// round 14
// speedup vs baseline: 1.5206x; 1.2937x over previous
#include <cuda_runtime.h>
#include <cuda_fp16.h>
#include <cstdint>

// Round 14: R13 + adaptive dropout hashing. Softmax is near-one-hot (logits
// N(0,128)); any P = exp(s - m_running) < 1e-9 contributes < 1e-9 to the
// output regardless of its dropout mask, so the threefry hash is computed only
// for warp-slots where any lane has P > 1e-9 (warp-coherent __any_sync gate).
// Cuts threefry work ~5x. Everything else identical to R13.
// B=4, Q=4096, NKV=4096, H=128, scale=+sqrt(128) folded into Q.

#define TB  256
#define BQ  64
#define BKV 64
#define HD  128
#define NQ  4096
#define NKV 4096
#define NT  (NKV/BKV)
#define NW32 (4*4096*64)   // uint32 (half2) count per split tensor

__device__ uint32_t gQh[NW32], gQl[NW32], gKh[NW32], gKl[NW32], gVh[NW32], gVl[NW32];

// smem byte offsets (per-CTA total 106 KB -> 2 CTAs/SM)
#define SM_QH  0u
#define SM_QL  16384u
#define SM_BUF 32768u
#define OF_KH  0u
#define OF_KL  16384u
#define OF_VH  32768u
#define OF_VL  49152u
#define SM_PH  98304u
#define SM_RED 106496u
#define SM_TOT 108544u

// ---- swizzled addressing (16B chunk ^ (row & 7)) ---------------------------
__device__ __forceinline__ uint32_t adr256(uint32_t base, int row, int colB) {
  uint32_t ch = ((uint32_t)colB >> 4) ^ ((uint32_t)row & 7u);
  return base + (uint32_t)row * 256u + ch * 16u + ((uint32_t)colB & 15u);
}
__device__ __forceinline__ uint32_t adr128(uint32_t base, int row, int colB) {
  uint32_t ch = ((uint32_t)colB >> 4) ^ ((uint32_t)row & 7u);
  return base + (uint32_t)row * 128u + ch * 16u + ((uint32_t)colB & 15u);
}
__device__ __forceinline__ uint32_t tadrA(uint32_t base, int r0, int c0, int lane) {
  int rr = r0 + (lane & 7) + ((lane >> 3) & 1) * 8;
  int cB = (c0 + ((lane >> 4) << 3)) * 2;
  return adr256(base, rr, cB);
}
__device__ __forceinline__ uint32_t tadrP(uint32_t base, int r0, int c0, int lane) {
  int rr = r0 + (lane & 7) + ((lane >> 3) & 1) * 8;
  int cB = (c0 + ((lane >> 4) << 3)) * 2;
  return adr128(base, rr, cB);
}
__device__ __forceinline__ uint32_t tadrVT(uint32_t base, int n0, int k0, int lane) {
  int rr = k0 + (lane & 7) + (((lane >> 4) & 1) << 3);
  int cB = (n0 + (((lane >> 3) & 1) << 3)) * 2;
  return adr256(base, rr, cB);
}
__device__ __forceinline__ void ldsm4(uint32_t* r, uint32_t a) {
  asm volatile("ldmatrix.sync.aligned.m8n8.x4.shared.b16 {%0,%1,%2,%3},[%4];"
               : "=r"(r[0]), "=r"(r[1]), "=r"(r[2]), "=r"(r[3]) : "r"(a));
}
__device__ __forceinline__ void ldsm4t(uint32_t* r, uint32_t a) {
  asm volatile("ldmatrix.sync.aligned.m8n8.x4.trans.shared.b16 {%0,%1,%2,%3},[%4];"
               : "=r"(r[0]), "=r"(r[1]), "=r"(r[2]), "=r"(r[3]) : "r"(a));
}
__device__ __forceinline__ void mma_(float* d, const uint32_t* a, uint32_t b0, uint32_t b1) {
  asm volatile(
    "mma.sync.aligned.m16n8k16.row.col.f32.f16.f16.f32 "
    "{%0,%1,%2,%3},{%4,%5,%6,%7},{%8,%9},{%0,%1,%2,%3};"
    : "+f"(d[0]), "+f"(d[1]), "+f"(d[2]), "+f"(d[3])
    : "r"(a[0]), "r"(a[1]), "r"(a[2]), "r"(a[3]), "r"(b0), "r"(b1));
}
__device__ __forceinline__ void sts32(uint32_t a, uint32_t x) {
  asm volatile("st.shared.b32 [%0],%1;" :: "r"(a), "r"(x));
}
__device__ __forceinline__ void cpa16(uint32_t d, const uint32_t* s) {
  asm volatile("cp.async.cg.shared.global [%0],[%1],16;" :: "r"(d), "l"(s));
}
__device__ __forceinline__ void cpa_commit() { asm volatile("cp.async.commit_group;"); }
__device__ __forceinline__ void cpa_wait0()  { asm volatile("cp.async.wait_group 0;"); }
__device__ __forceinline__ void barsub(int id) {
  asm volatile("bar.sync %0, 128;" :: "r"(id) : "memory");
}

__device__ __forceinline__ void splith(float a, float b, uint32_t& hi, uint32_t& lo) {
  __half2 h = __floats2half2_rn(a, b);
  float2 hf = __half22float2(h);
  __half2 l = __floats2half2_rn(a - hf.x, b - hf.y);
  hi = *reinterpret_cast<uint32_t*>(&h);
  lo = *reinterpret_cast<uint32_t*>(&l);
}
__device__ __forceinline__ uint32_t packh(float a, float b) {
  __half2 h = __floats2half2_rn(a, b);
  return *reinterpret_cast<uint32_t*>(&h);
}

// JAX threefry2x32-20, key (0,42), partitionable: counter (0,i), bits=x0^x1
__device__ __forceinline__ unsigned keep_mask(unsigned idx) {
  const unsigned ks1 = 42u, ks2 = 0x1BD11BDAu ^ 42u;
  unsigned x0 = 0u, x1 = idx + ks1;
#define TFR(r) { x0 += x1; x1 = __funnelshift_l(x1, x1, (r)); x1 ^= x0; }
  TFR(13) TFR(15) TFR(26) TFR(6)
  x0 += ks1; x1 += ks2 + 1u;
  TFR(17) TFR(29) TFR(16) TFR(24)
  x0 += ks2; x1 += 2u;
  TFR(13) TFR(15) TFR(26) TFR(6)
  x1 += ks1 + 3u;
  TFR(17) TFR(29) TFR(16) TFR(24)
  x0 += ks1; x1 += ks2 + 4u;
  TFR(13) TFR(15) TFR(26) TFR(6)
  x0 += ks2; x1 += 5u;
#undef TFR
  return (((x0 ^ x1) >> 9) < 7549747u) ? 1u : 0u;
}

// ---- pre-split pass: fp32 -> f16 hi/lo (Q scaled by sqrt(128)) -------------
__global__ void __launch_bounds__(512)
presplit_kernel(const float* __restrict__ Q, const float* __restrict__ K,
                const float* __restrict__ V) {
  int i = blockIdx.x * 512 + threadIdx.x;    // float4 index
  const float SC = 11.3137084989847603904f;
  uint32_t h0, l0, h1, l1;
  float4 q = reinterpret_cast<const float4*>(Q)[i];
  splith(q.x * SC, q.y * SC, h0, l0);
  splith(q.z * SC, q.w * SC, h1, l1);
  gQh[2*i] = h0; gQh[2*i+1] = h1; gQl[2*i] = l0; gQl[2*i+1] = l1;
  float4 k = reinterpret_cast<const float4*>(K)[i];
  splith(k.x, k.y, h0, l0);
  splith(k.z, k.w, h1, l1);
  gKh[2*i] = h0; gKh[2*i+1] = h1; gKl[2*i] = l0; gKl[2*i+1] = l1;
  float4 v = reinterpret_cast<const float4*>(V)[i];
  splith(v.x, v.y, h0, l0);
  splith(v.z, v.w, h1, l1);
  gVh[2*i] = h0; gVh[2*i+1] = h1; gVl[2*i] = l0; gVl[2*i+1] = l1;
}

// ---- helper: issue one KV tile's cp.asyncs (16 per thread at TB=256) -------
__device__ __forceinline__ void issue_tile(uint32_t bb, unsigned src, int tid) {
  #pragma unroll
  for (int it = 0; it < 4; ++it) {
    int c = tid + it * TB;                  // 0..1023
    int row = c >> 4, ch = c & 15;
    unsigned o = src + (unsigned)(row * 64 + ch * 4);
    cpa16(adr256(bb + OF_KH, row, ch * 16), gKh + o);
    cpa16(adr256(bb + OF_KL, row, ch * 16), gKl + o);
    cpa16(adr256(bb + OF_VH, row, ch * 16), gVh + o);
    cpa16(adr256(bb + OF_VL, row, ch * 16), gVl + o);
  }
}

__global__ void __launch_bounds__(TB, 2)
Model_56358560858161_kernel(float* __restrict__ Og) {
  extern __shared__ __align__(1024) char smem[];
  const uint32_t sb = (uint32_t)__cvta_generic_to_shared(smem);
  float2* RED = reinterpret_cast<float2*>(smem + SM_RED);   // [4 wc][64 rows]

  const int tid  = threadIdx.x;
  const int lane = tid & 31, w = tid >> 5;
  const int wr = w & 1, wc = w >> 1;        // 2 row-groups x 4 col-warps
  const int b  = blockIdx.x >> 6;
  const int q0 = (blockIdx.x & 63) * BQ;
  const unsigned gbase  = (unsigned)(b * NQ + q0);
  const unsigned qoff   = gbase * 64u;              // uint32 units
  const unsigned kvbase = (unsigned)(b * NKV) * 64u;

  // ---- prologue: Q (both halves) ------------------------------------------
  #pragma unroll
  for (int it = 0; it < 4; ++it) {
    int c = tid + it * TB;                  // 0..1023
    int row = c >> 4, ch = c & 15;
    unsigned o = qoff + (unsigned)(row * 64 + ch * 4);
    cpa16(adr256(sb + SM_QH, row, ch * 16), gQh + o);
    cpa16(adr256(sb + SM_QL, row, ch * 16), gQl + o);
  }
  cpa_commit();

  float m_[2][2], l_[2][2], OA[2][4][4];
  #pragma unroll
  for (int mt = 0; mt < 2; ++mt)
    #pragma unroll
    for (int h2 = 0; h2 < 2; ++h2) { m_[mt][h2] = -1e30f; l_[mt][h2] = 0.f; }
  #pragma unroll
  for (int mt = 0; mt < 2; ++mt)
    #pragma unroll
    for (int nt = 0; nt < 4; ++nt)
      #pragma unroll
      for (int e = 0; e < 4; ++e) OA[mt][nt][e] = 0.f;

  for (int jt = 0; jt < NT; ++jt) {
    __syncthreads();      // all warps done with tile jt-1's KV + P smem
    issue_tile(sb + SM_BUF, kvbase + (unsigned)jt * BKV * 64u, tid);
    cpa_commit();
    cpa_wait0();
    __syncthreads();      // tile jt visible
    const uint32_t bb = sb + SM_BUF;

    // ---- S = Q K^T: rows 32wr+{0,16}, cols 16wc ---------------------------
    float acc[2][2][4];
    #pragma unroll
    for (int mt = 0; mt < 2; ++mt)
      #pragma unroll
      for (int nt = 0; nt < 2; ++nt)
        #pragma unroll
        for (int e = 0; e < 4; ++e) acc[mt][nt][e] = 0.f;

    #pragma unroll
    for (int ks = 0; ks < 8; ++ks) {
      int k0 = ks * 16;
      uint32_t ah0[4], ah1[4], al0[4], al1[4], bh[4], bl[4];
      ldsm4(ah0, tadrA(sb + SM_QH, 32 * wr,      k0, lane));
      ldsm4(ah1, tadrA(sb + SM_QH, 32 * wr + 16, k0, lane));
      ldsm4(al0, tadrA(sb + SM_QL, 32 * wr,      k0, lane));
      ldsm4(al1, tadrA(sb + SM_QL, 32 * wr + 16, k0, lane));
      ldsm4(bh,  tadrA(bb + OF_KH, 16 * wc,      k0, lane));
      ldsm4(bl,  tadrA(bb + OF_KL, 16 * wc,      k0, lane));
      mma_(acc[0][0], ah0, bh[0], bh[2]); mma_(acc[0][1], ah0, bh[1], bh[3]);
      mma_(acc[1][0], ah1, bh[0], bh[2]); mma_(acc[1][1], ah1, bh[1], bh[3]);
      mma_(acc[0][0], ah0, bl[0], bl[2]); mma_(acc[0][1], ah0, bl[1], bl[3]);
      mma_(acc[1][0], ah1, bl[0], bl[2]); mma_(acc[1][1], ah1, bl[1], bl[3]);
      mma_(acc[0][0], al0, bh[0], bh[2]); mma_(acc[0][1], al0, bh[1], bh[3]);
      mma_(acc[1][0], al1, bh[0], bh[2]); mma_(acc[1][1], al1, bh[1], bh[3]);
    }

    // ---- softmax: warp-local (mw, sw); row-group barrier ------------------
    float mw[2][2];
    #pragma unroll
    for (int mt = 0; mt < 2; ++mt)
      #pragma unroll
      for (int h2 = 0; h2 < 2; ++h2) {
        float v0 = acc[mt][0][2*h2], v1 = acc[mt][0][2*h2+1];
        float v2 = acc[mt][1][2*h2], v3 = acc[mt][1][2*h2+1];
        float mx = fmaxf(fmaxf(v0, v1), fmaxf(v2, v3));
        mx = fmaxf(mx, __shfl_xor_sync(0xffffffffu, mx, 1));
        mx = fmaxf(mx, __shfl_xor_sync(0xffffffffu, mx, 2));
        mw[mt][h2] = mx;
        float s = 0.f;
        #pragma unroll
        for (int nt = 0; nt < 2; ++nt)
          #pragma unroll
          for (int e = 0; e < 2; ++e) {
            float ex = __expf(acc[mt][nt][2*h2+e] - mx);
            acc[mt][nt][2*h2+e] = ex;
            s += ex;
          }
        s += __shfl_xor_sync(0xffffffffu, s, 1);
        s += __shfl_xor_sync(0xffffffffu, s, 2);
        if ((lane & 3) == 0) {
          int row = 32 * wr + 16 * mt + 8 * h2 + (lane >> 2);
          RED[wc * 64 + row] = make_float2(mx, s);
        }
      }
    barsub(1 + wr);       // 4 warps of this row-group

    float corr[2][2], f_[2][2];
    #pragma unroll
    for (int mt = 0; mt < 2; ++mt)
      #pragma unroll
      for (int h2 = 0; h2 < 2; ++h2) {
        int row = 32 * wr + 16 * mt + 8 * h2 + (lane >> 2);
        float2 rw[4];
        #pragma unroll
        for (int w2 = 0; w2 < 4; ++w2) rw[w2] = RED[w2 * 64 + row];
        float mnew = m_[mt][h2];
        #pragma unroll
        for (int w2 = 0; w2 < 4; ++w2) mnew = fmaxf(mnew, rw[w2].x);
        float c_ = __expf(m_[mt][h2] - mnew);
        float ls = l_[mt][h2] * c_;
        #pragma unroll
        for (int w2 = 0; w2 < 4; ++w2) ls += rw[w2].y * __expf(rw[w2].x - mnew);
        corr[mt][h2] = c_;
        f_[mt][h2]   = __expf(mw[mt][h2] - mnew);
        l_[mt][h2] = ls;
        m_[mt][h2] = mnew;
      }

    // ---- adaptive dropout + P -> smem --------------------------------------
    // P = exp(s - m_running) < 1e-9 contributes < 1e-9 to the final output
    // regardless of its mask (corr<=1, l>=1): skip the hash for slots where
    // no lane needs it (warp-coherent vote; no divergence cost).
    const float THR = 1e-9f;
    #pragma unroll
    for (int mt = 0; mt < 2; ++mt)
      #pragma unroll
      for (int h2 = 0; h2 < 2; ++h2) {
        int row = 32 * wr + 16 * mt + 8 * h2 + (lane >> 2);
        float fr = f_[mt][h2];
        float p0 = acc[mt][0][2*h2]   * fr;
        float p1 = acc[mt][0][2*h2+1] * fr;
        float p2 = acc[mt][1][2*h2]   * fr;
        float p3 = acc[mt][1][2*h2+1] * fr;
        unsigned ib = (gbase + (unsigned)row) * (unsigned)NKV
                    + (unsigned)(jt * BKV + 16 * wc + 2 * (lane & 3));
        if (__any_sync(0xffffffffu, p0 > THR)) {
          if (!keep_mask(ib)) p0 = 0.f;
        } else p0 = 0.f;
        if (__any_sync(0xffffffffu, p1 > THR)) {
          if (!keep_mask(ib + 1u)) p1 = 0.f;
        } else p1 = 0.f;
        if (__any_sync(0xffffffffu, p2 > THR)) {
          if (!keep_mask(ib + 8u)) p2 = 0.f;
        } else p2 = 0.f;
        if (__any_sync(0xffffffffu, p3 > THR)) {
          if (!keep_mask(ib + 9u)) p3 = 0.f;
        } else p3 = 0.f;
        int colB = (16 * wc + 2 * (lane & 3)) * 2;
        sts32(adr128(sb + SM_PH, row, colB),      packh(p0, p1));
        sts32(adr128(sb + SM_PH, row, colB + 16), packh(p2, p3));
      }
    barsub(1 + wr);       // P rows of this group visible to its 4 warps

    // ---- O = O*corr + P V (V via ldmatrix.trans) --------------------------
    #pragma unroll
    for (int mt = 0; mt < 2; ++mt)
      #pragma unroll
      for (int nt = 0; nt < 4; ++nt)
        #pragma unroll
        for (int e = 0; e < 4; ++e) OA[mt][nt][e] *= corr[mt][e >> 1];

    #pragma unroll
    for (int ks = 0; ks < 4; ++ks) {
      int k0 = ks * 16;
      uint32_t ph0[4], ph1[4], vhA[4], vhB[4], vlA[4], vlB[4];
      ldsm4(ph0,  tadrP(sb + SM_PH, 32 * wr,      k0, lane));
      ldsm4(ph1,  tadrP(sb + SM_PH, 32 * wr + 16, k0, lane));
      ldsm4t(vhA, tadrVT(bb + OF_VH, 32 * wc,      k0, lane));
      ldsm4t(vhB, tadrVT(bb + OF_VH, 32 * wc + 16, k0, lane));
      ldsm4t(vlA, tadrVT(bb + OF_VL, 32 * wc,      k0, lane));
      ldsm4t(vlB, tadrVT(bb + OF_VL, 32 * wc + 16, k0, lane));
      mma_(OA[0][0], ph0, vhA[0], vhA[2]); mma_(OA[0][1], ph0, vhA[1], vhA[3]);
      mma_(OA[0][2], ph0, vhB[0], vhB[2]); mma_(OA[0][3], ph0, vhB[1], vhB[3]);
      mma_(OA[1][0], ph1, vhA[0], vhA[2]); mma_(OA[1][1], ph1, vhA[1], vhA[3]);
      mma_(OA[1][2], ph1, vhB[0], vhB[2]); mma_(OA[1][3], ph1, vhB[1], vhB[3]);
      mma_(OA[0][0], ph0, vlA[0], vlA[2]); mma_(OA[0][1], ph0, vlA[1], vlA[3]);
      mma_(OA[0][2], ph0, vlB[0], vlB[2]); mma_(OA[0][3], ph0, vlB[1], vlB[3]);
      mma_(OA[1][0], ph1, vlA[0], vlA[2]); mma_(OA[1][1], ph1, vlA[1], vlA[3]);
      mma_(OA[1][2], ph1, vlB[0], vlB[2]); mma_(OA[1][3], ph1, vlB[1], vlB[3]);
    }
  }

  // ---- epilogue ------------------------------------------------------------
  #pragma unroll
  for (int mt = 0; mt < 2; ++mt) {
    float inv0 = 1.0f / (l_[mt][0] * 0.9f);
    float inv1 = 1.0f / (l_[mt][1] * 0.9f);
    #pragma unroll
    for (int nt = 0; nt < 4; ++nt) {
      int col = 32 * wc + 8 * nt + 2 * (lane & 3);
      #pragma unroll
      for (int h2 = 0; h2 < 2; ++h2) {
        int row = 32 * wr + 16 * mt + 8 * h2 + (lane >> 2);
        float inv = h2 ? inv1 : inv0;
        float2 o;
        o.x = OA[mt][nt][2*h2]   * inv;
        o.y = OA[mt][nt][2*h2+1] * inv;
        *reinterpret_cast<float2*>(Og + (size_t)(gbase + row) * HD + col) = o;
      }
    }
  }
}

extern "C" void kernel_launch(void* const* d_in, const int* in_sizes, int n_in,
                              void* d_out, int out_size) {
  const float* Q = (const float*)d_in[0];
  const float* K = (const float*)d_in[1];
  const float* V = (const float*)d_in[2];
  float* O = (float*)d_out;
  (void)in_sizes; (void)n_in; (void)out_size;
  presplit_kernel<<<1024, 512>>>(Q, K, V);
  cudaFuncSetAttribute(Model_56358560858161_kernel,
                       cudaFuncAttributeMaxDynamicSharedMemorySize, (int)SM_TOT);
  Model_56358560858161_kernel<<<256, TB, SM_TOT>>>(O);
}

// round 15
// speedup vs baseline: 1.7932x; 1.1793x over previous
#include <cuda_runtime.h>
#include <cuda_fp16.h>
#include <cstdint>

// Round 15: R14 + (a) 1-term AV (V-hi only; V fp16 rounding ~1.4e-4 rel, in
// budget) -> 20% less tensor work; (b) V double-buffered + K prefetched after
// S phase -> cp.async latency fully hidden. 2 CTAs/SM kept (106 KB smem).
// Exact JAX threefry dropout with adaptive (P>1e-9) hashing.
// B=4, Q=4096, NKV=4096, H=128, scale=+sqrt(128) folded into Q.

#define TB  256
#define BQ  64
#define BKV 64
#define HD  128
#define NQ  4096
#define NKV 4096
#define NT  (NKV/BKV)
#define NW32 (4*4096*64)   // uint32 (half2) count per split tensor

__device__ uint32_t gQh[NW32], gQl[NW32], gKh[NW32], gKl[NW32], gVh[NW32];

// smem byte offsets (per-CTA total 106 KB -> 2 CTAs/SM)
#define SM_QH  0u
#define SM_QL  16384u
#define SM_KH  32768u
#define SM_KL  49152u
#define SM_VH0 65536u      // V hi, double-buffered (16 KB each)
#define SM_PH  98304u
#define SM_RED 106496u
#define SM_TOT 108544u

// ---- swizzled addressing (16B chunk ^ (row & 7)) ---------------------------
__device__ __forceinline__ uint32_t adr256(uint32_t base, int row, int colB) {
  uint32_t ch = ((uint32_t)colB >> 4) ^ ((uint32_t)row & 7u);
  return base + (uint32_t)row * 256u + ch * 16u + ((uint32_t)colB & 15u);
}
__device__ __forceinline__ uint32_t adr128(uint32_t base, int row, int colB) {
  uint32_t ch = ((uint32_t)colB >> 4) ^ ((uint32_t)row & 7u);
  return base + (uint32_t)row * 128u + ch * 16u + ((uint32_t)colB & 15u);
}
__device__ __forceinline__ uint32_t tadrA(uint32_t base, int r0, int c0, int lane) {
  int rr = r0 + (lane & 7) + ((lane >> 3) & 1) * 8;
  int cB = (c0 + ((lane >> 4) << 3)) * 2;
  return adr256(base, rr, cB);
}
__device__ __forceinline__ uint32_t tadrP(uint32_t base, int r0, int c0, int lane) {
  int rr = r0 + (lane & 7) + ((lane >> 3) & 1) * 8;
  int cB = (c0 + ((lane >> 4) << 3)) * 2;
  return adr128(base, rr, cB);
}
__device__ __forceinline__ uint32_t tadrVT(uint32_t base, int n0, int k0, int lane) {
  int rr = k0 + (lane & 7) + (((lane >> 4) & 1) << 3);
  int cB = (n0 + (((lane >> 3) & 1) << 3)) * 2;
  return adr256(base, rr, cB);
}
__device__ __forceinline__ void ldsm4(uint32_t* r, uint32_t a) {
  asm volatile("ldmatrix.sync.aligned.m8n8.x4.shared.b16 {%0,%1,%2,%3},[%4];"
               : "=r"(r[0]), "=r"(r[1]), "=r"(r[2]), "=r"(r[3]) : "r"(a));
}
__device__ __forceinline__ void ldsm4t(uint32_t* r, uint32_t a) {
  asm volatile("ldmatrix.sync.aligned.m8n8.x4.trans.shared.b16 {%0,%1,%2,%3},[%4];"
               : "=r"(r[0]), "=r"(r[1]), "=r"(r[2]), "=r"(r[3]) : "r"(a));
}
__device__ __forceinline__ void mma_(float* d, const uint32_t* a, uint32_t b0, uint32_t b1) {
  asm volatile(
    "mma.sync.aligned.m16n8k16.row.col.f32.f16.f16.f32 "
    "{%0,%1,%2,%3},{%4,%5,%6,%7},{%8,%9},{%0,%1,%2,%3};"
    : "+f"(d[0]), "+f"(d[1]), "+f"(d[2]), "+f"(d[3])
    : "r"(a[0]), "r"(a[1]), "r"(a[2]), "r"(a[3]), "r"(b0), "r"(b1));
}
__device__ __forceinline__ void sts32(uint32_t a, uint32_t x) {
  asm volatile("st.shared.b32 [%0],%1;" :: "r"(a), "r"(x));
}
__device__ __forceinline__ void cpa16(uint32_t d, const uint32_t* s) {
  asm volatile("cp.async.cg.shared.global [%0],[%1],16;" :: "r"(d), "l"(s));
}
__device__ __forceinline__ void cpa_commit() { asm volatile("cp.async.commit_group;"); }
__device__ __forceinline__ void cpa_wait0()  { asm volatile("cp.async.wait_group 0;"); }
__device__ __forceinline__ void barsub(int id) {
  asm volatile("bar.sync %0, 128;" :: "r"(id) : "memory");
}

__device__ __forceinline__ void splith(float a, float b, uint32_t& hi, uint32_t& lo) {
  __half2 h = __floats2half2_rn(a, b);
  float2 hf = __half22float2(h);
  __half2 l = __floats2half2_rn(a - hf.x, b - hf.y);
  hi = *reinterpret_cast<uint32_t*>(&h);
  lo = *reinterpret_cast<uint32_t*>(&l);
}
__device__ __forceinline__ uint32_t packh(float a, float b) {
  __half2 h = __floats2half2_rn(a, b);
  return *reinterpret_cast<uint32_t*>(&h);
}

// JAX threefry2x32-20, key (0,42), partitionable: counter (0,i), bits=x0^x1
__device__ __forceinline__ unsigned keep_mask(unsigned idx) {
  const unsigned ks1 = 42u, ks2 = 0x1BD11BDAu ^ 42u;
  unsigned x0 = 0u, x1 = idx + ks1;
#define TFR(r) { x0 += x1; x1 = __funnelshift_l(x1, x1, (r)); x1 ^= x0; }
  TFR(13) TFR(15) TFR(26) TFR(6)
  x0 += ks1; x1 += ks2 + 1u;
  TFR(17) TFR(29) TFR(16) TFR(24)
  x0 += ks2; x1 += 2u;
  TFR(13) TFR(15) TFR(26) TFR(6)
  x1 += ks1 + 3u;
  TFR(17) TFR(29) TFR(16) TFR(24)
  x0 += ks1; x1 += ks2 + 4u;
  TFR(13) TFR(15) TFR(26) TFR(6)
  x0 += ks2; x1 += 5u;
#undef TFR
  return (((x0 ^ x1) >> 9) < 7549747u) ? 1u : 0u;
}

// ---- pre-split pass: fp32 -> f16 (Q scaled; Q/K hi+lo, V hi only) ----------
__global__ void __launch_bounds__(512)
presplit_kernel(const float* __restrict__ Q, const float* __restrict__ K,
                const float* __restrict__ V) {
  int i = blockIdx.x * 512 + threadIdx.x;    // float4 index
  const float SC = 11.3137084989847603904f;
  uint32_t h0, l0, h1, l1;
  float4 q = reinterpret_cast<const float4*>(Q)[i];
  splith(q.x * SC, q.y * SC, h0, l0);
  splith(q.z * SC, q.w * SC, h1, l1);
  gQh[2*i] = h0; gQh[2*i+1] = h1; gQl[2*i] = l0; gQl[2*i+1] = l1;
  float4 k = reinterpret_cast<const float4*>(K)[i];
  splith(k.x, k.y, h0, l0);
  splith(k.z, k.w, h1, l1);
  gKh[2*i] = h0; gKh[2*i+1] = h1; gKl[2*i] = l0; gKl[2*i+1] = l1;
  float4 v = reinterpret_cast<const float4*>(V)[i];
  gVh[2*i]   = packh(v.x, v.y);
  gVh[2*i+1] = packh(v.z, v.w);
}

// ---- cp.async issue helpers (TB=256) ---------------------------------------
__device__ __forceinline__ void issue_V(uint32_t vb, unsigned src, int tid) {
  #pragma unroll
  for (int it = 0; it < 4; ++it) {
    int c = tid + it * TB;                  // 0..1023
    int row = c >> 4, ch = c & 15;
    cpa16(adr256(vb, row, ch * 16), gVh + src + (unsigned)(row * 64 + ch * 4));
  }
}
__device__ __forceinline__ void issue_K(uint32_t sbase, unsigned src, int tid) {
  #pragma unroll
  for (int it = 0; it < 4; ++it) {
    int c = tid + it * TB;
    int row = c >> 4, ch = c & 15;
    unsigned o = src + (unsigned)(row * 64 + ch * 4);
    cpa16(adr256(sbase + SM_KH, row, ch * 16), gKh + o);
    cpa16(adr256(sbase + SM_KL, row, ch * 16), gKl + o);
  }
}

__global__ void __launch_bounds__(TB, 2)
Model_56358560858161_kernel(float* __restrict__ Og) {
  extern __shared__ __align__(1024) char smem[];
  const uint32_t sb = (uint32_t)__cvta_generic_to_shared(smem);
  float2* RED = reinterpret_cast<float2*>(smem + SM_RED);   // [4 wc][64 rows]

  const int tid  = threadIdx.x;
  const int lane = tid & 31, w = tid >> 5;
  const int wr = w & 1, wc = w >> 1;        // 2 row-groups x 4 col-warps
  const int b  = blockIdx.x >> 6;
  const int q0 = (blockIdx.x & 63) * BQ;
  const unsigned gbase  = (unsigned)(b * NQ + q0);
  const unsigned qoff   = gbase * 64u;              // uint32 units
  const unsigned kvbase = (unsigned)(b * NKV) * 64u;

  // ---- prologue: Q (both halves) + K(0) + V(0) ----------------------------
  #pragma unroll
  for (int it = 0; it < 4; ++it) {
    int c = tid + it * TB;                  // 0..1023
    int row = c >> 4, ch = c & 15;
    unsigned o = qoff + (unsigned)(row * 64 + ch * 4);
    cpa16(adr256(sb + SM_QH, row, ch * 16), gQh + o);
    cpa16(adr256(sb + SM_QL, row, ch * 16), gQl + o);
  }
  issue_K(sb, kvbase, tid);
  issue_V(sb + SM_VH0, kvbase, tid);
  cpa_commit();

  float m_[2][2], l_[2][2], OA[2][4][4];
  #pragma unroll
  for (int mt = 0; mt < 2; ++mt)
    #pragma unroll
    for (int h2 = 0; h2 < 2; ++h2) { m_[mt][h2] = -1e30f; l_[mt][h2] = 0.f; }
  #pragma unroll
  for (int mt = 0; mt < 2; ++mt)
    #pragma unroll
    for (int nt = 0; nt < 4; ++nt)
      #pragma unroll
      for (int e = 0; e < 4; ++e) OA[mt][nt][e] = 0.f;

  for (int jt = 0; jt < NT; ++jt) {
    cpa_wait0();
    __syncthreads();      // K(jt),V(jt) resident; all warps past AV(jt-1)

    // V(jt+1) into the buffer AV(jt-1) vacated (free by the sync above)
    if (jt + 1 < NT)
      issue_V(sb + SM_VH0 + (uint32_t)(((jt + 1) & 1) ? 16384u : 0u),
              kvbase + (unsigned)(jt + 1) * BKV * 64u, tid);
    cpa_commit();

    // ---- S = Q K^T: rows 32wr+{0,16}, cols 16wc ---------------------------
    float acc[2][2][4];
    #pragma unroll
    for (int mt = 0; mt < 2; ++mt)
      #pragma unroll
      for (int nt = 0; nt < 2; ++nt)
        #pragma unroll
        for (int e = 0; e < 4; ++e) acc[mt][nt][e] = 0.f;

    #pragma unroll
    for (int ks = 0; ks < 8; ++ks) {
      int k0 = ks * 16;
      uint32_t ah0[4], ah1[4], al0[4], al1[4], bh[4], bl[4];
      ldsm4(ah0, tadrA(sb + SM_QH, 32 * wr,      k0, lane));
      ldsm4(ah1, tadrA(sb + SM_QH, 32 * wr + 16, k0, lane));
      ldsm4(al0, tadrA(sb + SM_QL, 32 * wr,      k0, lane));
      ldsm4(al1, tadrA(sb + SM_QL, 32 * wr + 16, k0, lane));
      ldsm4(bh,  tadrA(sb + SM_KH, 16 * wc,      k0, lane));
      ldsm4(bl,  tadrA(sb + SM_KL, 16 * wc,      k0, lane));
      mma_(acc[0][0], ah0, bh[0], bh[2]); mma_(acc[0][1], ah0, bh[1], bh[3]);
      mma_(acc[1][0], ah1, bh[0], bh[2]); mma_(acc[1][1], ah1, bh[1], bh[3]);
      mma_(acc[0][0], ah0, bl[0], bl[2]); mma_(acc[0][1], ah0, bl[1], bl[3]);
      mma_(acc[1][0], ah1, bl[0], bl[2]); mma_(acc[1][1], ah1, bl[1], bl[3]);
      mma_(acc[0][0], al0, bh[0], bh[2]); mma_(acc[0][1], al0, bh[1], bh[3]);
      mma_(acc[1][0], al1, bh[0], bh[2]); mma_(acc[1][1], al1, bh[1], bh[3]);
    }

    __syncthreads();      // all warps done reading K(jt)
    if (jt + 1 < NT)
      issue_K(sb, kvbase + (unsigned)(jt + 1) * BKV * 64u, tid);
    cpa_commit();         // K(jt+1) flies under softmax+P+AV

    // ---- softmax: warp-local (mw, sw); row-group barrier ------------------
    float mw[2][2];
    #pragma unroll
    for (int mt = 0; mt < 2; ++mt)
      #pragma unroll
      for (int h2 = 0; h2 < 2; ++h2) {
        float v0 = acc[mt][0][2*h2], v1 = acc[mt][0][2*h2+1];
        float v2 = acc[mt][1][2*h2], v3 = acc[mt][1][2*h2+1];
        float mx = fmaxf(fmaxf(v0, v1), fmaxf(v2, v3));
        mx = fmaxf(mx, __shfl_xor_sync(0xffffffffu, mx, 1));
        mx = fmaxf(mx, __shfl_xor_sync(0xffffffffu, mx, 2));
        mw[mt][h2] = mx;
        float s = 0.f;
        #pragma unroll
        for (int nt = 0; nt < 2; ++nt)
          #pragma unroll
          for (int e = 0; e < 2; ++e) {
            float ex = __expf(acc[mt][nt][2*h2+e] - mx);
            acc[mt][nt][2*h2+e] = ex;
            s += ex;
          }
        s += __shfl_xor_sync(0xffffffffu, s, 1);
        s += __shfl_xor_sync(0xffffffffu, s, 2);
        if ((lane & 3) == 0) {
          int row = 32 * wr + 16 * mt + 8 * h2 + (lane >> 2);
          RED[wc * 64 + row] = make_float2(mx, s);
        }
      }
    barsub(1 + wr);       // 4 warps of this row-group

    float corr[2][2], f_[2][2];
    #pragma unroll
    for (int mt = 0; mt < 2; ++mt)
      #pragma unroll
      for (int h2 = 0; h2 < 2; ++h2) {
        int row = 32 * wr + 16 * mt + 8 * h2 + (lane >> 2);
        float2 rw[4];
        #pragma unroll
        for (int w2 = 0; w2 < 4; ++w2) rw[w2] = RED[w2 * 64 + row];
        float mnew = m_[mt][h2];
        #pragma unroll
        for (int w2 = 0; w2 < 4; ++w2) mnew = fmaxf(mnew, rw[w2].x);
        float c_ = __expf(m_[mt][h2] - mnew);
        float ls = l_[mt][h2] * c_;
        #pragma unroll
        for (int w2 = 0; w2 < 4; ++w2) ls += rw[w2].y * __expf(rw[w2].x - mnew);
        corr[mt][h2] = c_;
        f_[mt][h2]   = __expf(mw[mt][h2] - mnew);
        l_[mt][h2] = ls;
        m_[mt][h2] = mnew;
      }

    // ---- adaptive dropout + P -> smem --------------------------------------
    const float THR = 1e-9f;
    #pragma unroll
    for (int mt = 0; mt < 2; ++mt)
      #pragma unroll
      for (int h2 = 0; h2 < 2; ++h2) {
        int row = 32 * wr + 16 * mt + 8 * h2 + (lane >> 2);
        float fr = f_[mt][h2];
        float p0 = acc[mt][0][2*h2]   * fr;
        float p1 = acc[mt][0][2*h2+1] * fr;
        float p2 = acc[mt][1][2*h2]   * fr;
        float p3 = acc[mt][1][2*h2+1] * fr;
        unsigned ib = (gbase + (unsigned)row) * (unsigned)NKV
                    + (unsigned)(jt * BKV + 16 * wc + 2 * (lane & 3));
        if (__any_sync(0xffffffffu, p0 > THR)) {
          if (!keep_mask(ib)) p0 = 0.f;
        } else p0 = 0.f;
        if (__any_sync(0xffffffffu, p1 > THR)) {
          if (!keep_mask(ib + 1u)) p1 = 0.f;
        } else p1 = 0.f;
        if (__any_sync(0xffffffffu, p2 > THR)) {
          if (!keep_mask(ib + 8u)) p2 = 0.f;
        } else p2 = 0.f;
        if (__any_sync(0xffffffffu, p3 > THR)) {
          if (!keep_mask(ib + 9u)) p3 = 0.f;
        } else p3 = 0.f;
        int colB = (16 * wc + 2 * (lane & 3)) * 2;
        sts32(adr128(sb + SM_PH, row, colB),      packh(p0, p1));
        sts32(adr128(sb + SM_PH, row, colB + 16), packh(p2, p3));
      }
    barsub(1 + wr);       // P rows of this group visible to its 4 warps

    // ---- O = O*corr + P V (V-hi only, ldmatrix.trans) ---------------------
    const uint32_t vb = sb + SM_VH0 + (uint32_t)((jt & 1) ? 16384u : 0u);
    #pragma unroll
    for (int mt = 0; mt < 2; ++mt)
      #pragma unroll
      for (int nt = 0; nt < 4; ++nt)
        #pragma unroll
        for (int e = 0; e < 4; ++e) OA[mt][nt][e] *= corr[mt][e >> 1];

    #pragma unroll
    for (int ks = 0; ks < 4; ++ks) {
      int k0 = ks * 16;
      uint32_t ph0[4], ph1[4], vhA[4], vhB[4];
      ldsm4(ph0,  tadrP(sb + SM_PH, 32 * wr,      k0, lane));
      ldsm4(ph1,  tadrP(sb + SM_PH, 32 * wr + 16, k0, lane));
      ldsm4t(vhA, tadrVT(vb, 32 * wc,      k0, lane));
      ldsm4t(vhB, tadrVT(vb, 32 * wc + 16, k0, lane));
      mma_(OA[0][0], ph0, vhA[0], vhA[2]); mma_(OA[0][1], ph0, vhA[1], vhA[3]);
      mma_(OA[0][2], ph0, vhB[0], vhB[2]); mma_(OA[0][3], ph0, vhB[1], vhB[3]);
      mma_(OA[1][0], ph1, vhA[0], vhA[2]); mma_(OA[1][1], ph1, vhA[1], vhA[3]);
      mma_(OA[1][2], ph1, vhB[0], vhB[2]); mma_(OA[1][3], ph1, vhB[1], vhB[3]);
    }
  }

  // ---- epilogue ------------------------------------------------------------
  #pragma unroll
  for (int mt = 0; mt < 2; ++mt) {
    float inv0 = 1.0f / (l_[mt][0] * 0.9f);
    float inv1 = 1.0f / (l_[mt][1] * 0.9f);
    #pragma unroll
    for (int nt = 0; nt < 4; ++nt) {
      int col = 32 * wc + 8 * nt + 2 * (lane & 3);
      #pragma unroll
      for (int h2 = 0; h2 < 2; ++h2) {
        int row = 32 * wr + 16 * mt + 8 * h2 + (lane >> 2);
        float inv = h2 ? inv1 : inv0;
        float2 o;
        o.x = OA[mt][nt][2*h2]   * inv;
        o.y = OA[mt][nt][2*h2+1] * inv;
        *reinterpret_cast<float2*>(Og + (size_t)(gbase + row) * HD + col) = o;
      }
    }
  }
}

extern "C" void kernel_launch(void* const* d_in, const int* in_sizes, int n_in,
                              void* d_out, int out_size) {
  const float* Q = (const float*)d_in[0];
  const float* K = (const float*)d_in[1];
  const float* V = (const float*)d_in[2];
  float* O = (float*)d_out;
  (void)in_sizes; (void)n_in; (void)out_size;
  presplit_kernel<<<1024, 512>>>(Q, K, V);
  cudaFuncSetAttribute(Model_56358560858161_kernel,
                       cudaFuncAttributeMaxDynamicSharedMemorySize, (int)SM_TOT);
  Model_56358560858161_kernel<<<256, TB, SM_TOT>>>(O);
}

// round 16
// speedup vs baseline: 1.9807x; 1.1046x over previous
#include <cuda_runtime.h>
#include <cuda_fp16.h>
#include <cstdint>

// Round 16: R15 + (a) closed-form swizzled ldsm addressing (base + ((ks<<5)^cX)
// for A/P operands, base + ks*4096 for V) — removes ~250 alu ops/tile/thread;
// (b) log2-domain softmax: log2(e) folded into Q scale, exp via bare ex2.approx;
// (c) THR 1e-8. Structure identical to R15 (2 CTAs/SM, V double-buffered,
// K prefetched post-S, adaptive threefry).
// B=4, Q=4096, NKV=4096, H=128, scale=+sqrt(128).

#define TB  256
#define BQ  64
#define BKV 64
#define HD  128
#define NQ  4096
#define NKV 4096
#define NT  (NKV/BKV)
#define NW32 (4*4096*64)

__device__ uint32_t gQh[NW32], gQl[NW32], gKh[NW32], gKl[NW32], gVh[NW32];

#define SM_QH  0u
#define SM_QL  16384u
#define SM_KH  32768u
#define SM_KL  49152u
#define SM_VH0 65536u      // V hi, double-buffered (16 KB each)
#define SM_PH  98304u
#define SM_RED 106496u
#define SM_TOT 108544u

__device__ __forceinline__ uint32_t adr256(uint32_t base, int row, int colB) {
  uint32_t ch = ((uint32_t)colB >> 4) ^ ((uint32_t)row & 7u);
  return base + (uint32_t)row * 256u + ch * 16u + ((uint32_t)colB & 15u);
}
__device__ __forceinline__ uint32_t adr128(uint32_t base, int row, int colB) {
  uint32_t ch = ((uint32_t)colB >> 4) ^ ((uint32_t)row & 7u);
  return base + (uint32_t)row * 128u + ch * 16u + ((uint32_t)colB & 15u);
}
__device__ __forceinline__ void ldsm4(uint32_t* r, uint32_t a) {
  asm volatile("ldmatrix.sync.aligned.m8n8.x4.shared.b16 {%0,%1,%2,%3},[%4];"
               : "=r"(r[0]), "=r"(r[1]), "=r"(r[2]), "=r"(r[3]) : "r"(a));
}
__device__ __forceinline__ void ldsm4t(uint32_t* r, uint32_t a) {
  asm volatile("ldmatrix.sync.aligned.m8n8.x4.trans.shared.b16 {%0,%1,%2,%3},[%4];"
               : "=r"(r[0]), "=r"(r[1]), "=r"(r[2]), "=r"(r[3]) : "r"(a));
}
__device__ __forceinline__ void mma_(float* d, const uint32_t* a, uint32_t b0, uint32_t b1) {
  asm volatile(
    "mma.sync.aligned.m16n8k16.row.col.f32.f16.f16.f32 "
    "{%0,%1,%2,%3},{%4,%5,%6,%7},{%8,%9},{%0,%1,%2,%3};"
    : "+f"(d[0]), "+f"(d[1]), "+f"(d[2]), "+f"(d[3])
    : "r"(a[0]), "r"(a[1]), "r"(a[2]), "r"(a[3]), "r"(b0), "r"(b1));
}
__device__ __forceinline__ void sts32(uint32_t a, uint32_t x) {
  asm volatile("st.shared.b32 [%0],%1;" :: "r"(a), "r"(x));
}
__device__ __forceinline__ void cpa16(uint32_t d, const uint32_t* s) {
  asm volatile("cp.async.cg.shared.global [%0],[%1],16;" :: "r"(d), "l"(s));
}
__device__ __forceinline__ void cpa_commit() { asm volatile("cp.async.commit_group;"); }
__device__ __forceinline__ void cpa_wait0()  { asm volatile("cp.async.wait_group 0;"); }
__device__ __forceinline__ void barsub(int id) {
  asm volatile("bar.sync %0, 128;" :: "r"(id) : "memory");
}
__device__ __forceinline__ float ex2(float x) {
  float r; asm("ex2.approx.ftz.f32 %0, %1;" : "=f"(r) : "f"(x)); return r;
}
__device__ __forceinline__ void splith(float a, float b, uint32_t& hi, uint32_t& lo) {
  __half2 h = __floats2half2_rn(a, b);
  float2 hf = __half22float2(h);
  __half2 l = __floats2half2_rn(a - hf.x, b - hf.y);
  hi = *reinterpret_cast<uint32_t*>(&h);
  lo = *reinterpret_cast<uint32_t*>(&l);
}
__device__ __forceinline__ uint32_t packh(float a, float b) {
  __half2 h = __floats2half2_rn(a, b);
  return *reinterpret_cast<uint32_t*>(&h);
}

// JAX threefry2x32-20, key (0,42), partitionable: counter (0,i), bits=x0^x1
__device__ __forceinline__ unsigned keep_mask(unsigned idx) {
  const unsigned ks1 = 42u, ks2 = 0x1BD11BDAu ^ 42u;
  unsigned x0 = 0u, x1 = idx + ks1;
#define TFR(r) { x0 += x1; x1 = __funnelshift_l(x1, x1, (r)); x1 ^= x0; }
  TFR(13) TFR(15) TFR(26) TFR(6)
  x0 += ks1; x1 += ks2 + 1u;
  TFR(17) TFR(29) TFR(16) TFR(24)
  x0 += ks2; x1 += 2u;
  TFR(13) TFR(15) TFR(26) TFR(6)
  x1 += ks1 + 3u;
  TFR(17) TFR(29) TFR(16) TFR(24)
  x0 += ks1; x1 += ks2 + 4u;
  TFR(13) TFR(15) TFR(26) TFR(6)
  x0 += ks2; x1 += 5u;
#undef TFR
  return (((x0 ^ x1) >> 9) < 7549747u) ? 1u : 0u;
}

// ---- pre-split: fp32 -> f16 (Q scaled by sqrt(128)*log2(e); V hi only) -----
__global__ void __launch_bounds__(512)
presplit_kernel(const float* __restrict__ Q, const float* __restrict__ K,
                const float* __restrict__ V) {
  int i = blockIdx.x * 512 + threadIdx.x;
  const float SC2 = 16.32223106385f;   // sqrt(128) * log2(e)
  uint32_t h0, l0, h1, l1;
  float4 q = reinterpret_cast<const float4*>(Q)[i];
  splith(q.x * SC2, q.y * SC2, h0, l0);
  splith(q.z * SC2, q.w * SC2, h1, l1);
  gQh[2*i] = h0; gQh[2*i+1] = h1; gQl[2*i] = l0; gQl[2*i+1] = l1;
  float4 k = reinterpret_cast<const float4*>(K)[i];
  splith(k.x, k.y, h0, l0);
  splith(k.z, k.w, h1, l1);
  gKh[2*i] = h0; gKh[2*i+1] = h1; gKl[2*i] = l0; gKl[2*i+1] = l1;
  float4 v = reinterpret_cast<const float4*>(V)[i];
  gVh[2*i]   = packh(v.x, v.y);
  gVh[2*i+1] = packh(v.z, v.w);
}

__device__ __forceinline__ void issue_V(uint32_t vb, unsigned src, int tid) {
  #pragma unroll
  for (int it = 0; it < 4; ++it) {
    int c = tid + it * TB;
    int row = c >> 4, ch = c & 15;
    cpa16(adr256(vb, row, ch * 16), gVh + src + (unsigned)(row * 64 + ch * 4));
  }
}
__device__ __forceinline__ void issue_K(uint32_t sbase, unsigned src, int tid) {
  #pragma unroll
  for (int it = 0; it < 4; ++it) {
    int c = tid + it * TB;
    int row = c >> 4, ch = c & 15;
    unsigned o = src + (unsigned)(row * 64 + ch * 4);
    cpa16(adr256(sbase + SM_KH, row, ch * 16), gKh + o);
    cpa16(adr256(sbase + SM_KL, row, ch * 16), gKl + o);
  }
}

__global__ void __launch_bounds__(TB, 2)
Model_56358560858161_kernel(float* __restrict__ Og) {
  extern __shared__ __align__(1024) char smem[];
  const uint32_t sb = (uint32_t)__cvta_generic_to_shared(smem);
  float2* RED = reinterpret_cast<float2*>(smem + SM_RED);   // [4 wc][64 rows]

  const int tid  = threadIdx.x;
  const int lane = tid & 31, w = tid >> 5;
  const int wr = w & 1, wc = w >> 1;        // 2 row-groups x 4 col-warps
  const int b  = blockIdx.x >> 6;
  const int q0 = (blockIdx.x & 63) * BQ;
  const unsigned gbase  = (unsigned)(b * NQ + q0);
  const unsigned qoff   = gbase * 64u;
  const unsigned kvbase = (unsigned)(b * NKV) * 64u;

  // ---- closed-form ldsm address bases --------------------------------------
  const int la7 = lane & 7, e8 = (lane >> 3) & 1, e16 = lane >> 4;
  const int rrA = la7 + e8 * 8;                       // A-frag row-in-16
  const uint32_t cXA = (uint32_t)((la7 ^ e16) << 4);  // swizzle XOR constant
  const uint32_t bQH0 = sb + SM_QH + (uint32_t)(32 * wr + rrA) * 256u;
  const uint32_t bQH1 = bQH0 + 4096u;
  const uint32_t bQL0 = sb + SM_QL + (uint32_t)(32 * wr + rrA) * 256u;
  const uint32_t bQL1 = bQL0 + 4096u;
  const uint32_t bKH  = sb + SM_KH + (uint32_t)(16 * wc + rrA) * 256u;
  const uint32_t bKL  = sb + SM_KL + (uint32_t)(16 * wc + rrA) * 256u;
  const uint32_t bP0  = sb + SM_PH + (uint32_t)(32 * wr + rrA) * 128u;
  const uint32_t bP1  = bP0 + 2048u;
  // V (trans): row = 16ks + la7 + 8*e16 ; col block n0 + 8*e8 ; affine in ks
  const int rbV = la7 + e16 * 8;
  const uint32_t bVA_off = (uint32_t)rbV * 256u
      + (uint32_t)((((32 * wc) >> 3) + e8) ^ la7) * 16u;
  const uint32_t bVB_off = (uint32_t)rbV * 256u
      + (uint32_t)(((((32 * wc) + 16) >> 3) + e8) ^ la7) * 16u;

  // ---- prologue: Q (both halves) + K(0) + V(0) ----------------------------
  #pragma unroll
  for (int it = 0; it < 4; ++it) {
    int c = tid + it * TB;
    int row = c >> 4, ch = c & 15;
    unsigned o = qoff + (unsigned)(row * 64 + ch * 4);
    cpa16(adr256(sb + SM_QH, row, ch * 16), gQh + o);
    cpa16(adr256(sb + SM_QL, row, ch * 16), gQl + o);
  }
  issue_K(sb, kvbase, tid);
  issue_V(sb + SM_VH0, kvbase, tid);
  cpa_commit();

  float m_[2][2], l_[2][2], OA[2][4][4];
  #pragma unroll
  for (int mt = 0; mt < 2; ++mt)
    #pragma unroll
    for (int h2 = 0; h2 < 2; ++h2) { m_[mt][h2] = -1e30f; l_[mt][h2] = 0.f; }
  #pragma unroll
  for (int mt = 0; mt < 2; ++mt)
    #pragma unroll
    for (int nt = 0; nt < 4; ++nt)
      #pragma unroll
      for (int e = 0; e < 4; ++e) OA[mt][nt][e] = 0.f;

  for (int jt = 0; jt < NT; ++jt) {
    cpa_wait0();
    __syncthreads();      // K(jt),V(jt) resident; all warps past AV(jt-1)

    if (jt + 1 < NT)
      issue_V(sb + SM_VH0 + (uint32_t)(((jt + 1) & 1) ? 16384u : 0u),
              kvbase + (unsigned)(jt + 1) * BKV * 64u, tid);
    cpa_commit();

    // ---- S = Q K^T -------------------------------------------------------
    float acc[2][2][4];
    #pragma unroll
    for (int mt = 0; mt < 2; ++mt)
      #pragma unroll
      for (int nt = 0; nt < 2; ++nt)
        #pragma unroll
        for (int e = 0; e < 4; ++e) acc[mt][nt][e] = 0.f;

    #pragma unroll
    for (int ks = 0; ks < 8; ++ks) {
      uint32_t ofs = ((uint32_t)ks << 5) ^ cXA;
      uint32_t ah0[4], ah1[4], al0[4], al1[4], bh[4], bl[4];
      ldsm4(ah0, bQH0 + ofs);
      ldsm4(ah1, bQH1 + ofs);
      ldsm4(al0, bQL0 + ofs);
      ldsm4(al1, bQL1 + ofs);
      ldsm4(bh,  bKH  + ofs);
      ldsm4(bl,  bKL  + ofs);
      mma_(acc[0][0], ah0, bh[0], bh[2]); mma_(acc[0][1], ah0, bh[1], bh[3]);
      mma_(acc[1][0], ah1, bh[0], bh[2]); mma_(acc[1][1], ah1, bh[1], bh[3]);
      mma_(acc[0][0], ah0, bl[0], bl[2]); mma_(acc[0][1], ah0, bl[1], bl[3]);
      mma_(acc[1][0], ah1, bl[0], bl[2]); mma_(acc[1][1], ah1, bl[1], bl[3]);
      mma_(acc[0][0], al0, bh[0], bh[2]); mma_(acc[0][1], al0, bh[1], bh[3]);
      mma_(acc[1][0], al1, bh[0], bh[2]); mma_(acc[1][1], al1, bh[1], bh[3]);
    }

    __syncthreads();      // all warps done reading K(jt)
    if (jt + 1 < NT)
      issue_K(sb, kvbase + (unsigned)(jt + 1) * BKV * 64u, tid);
    cpa_commit();         // K(jt+1) flies under softmax+P+AV

    // ---- softmax (log2 domain): warp-local (mw, sw) -----------------------
    float mw[2][2];
    #pragma unroll
    for (int mt = 0; mt < 2; ++mt)
      #pragma unroll
      for (int h2 = 0; h2 < 2; ++h2) {
        float v0 = acc[mt][0][2*h2], v1 = acc[mt][0][2*h2+1];
        float v2 = acc[mt][1][2*h2], v3 = acc[mt][1][2*h2+1];
        float mx = fmaxf(fmaxf(v0, v1), fmaxf(v2, v3));
        mx = fmaxf(mx, __shfl_xor_sync(0xffffffffu, mx, 1));
        mx = fmaxf(mx, __shfl_xor_sync(0xffffffffu, mx, 2));
        mw[mt][h2] = mx;
        float s = 0.f;
        #pragma unroll
        for (int nt = 0; nt < 2; ++nt)
          #pragma unroll
          for (int e = 0; e < 2; ++e) {
            float ex = ex2(acc[mt][nt][2*h2+e] - mx);
            acc[mt][nt][2*h2+e] = ex;
            s += ex;
          }
        s += __shfl_xor_sync(0xffffffffu, s, 1);
        s += __shfl_xor_sync(0xffffffffu, s, 2);
        if ((lane & 3) == 0) {
          int row = 32 * wr + 16 * mt + 8 * h2 + (lane >> 2);
          RED[wc * 64 + row] = make_float2(mx, s);
        }
      }
    barsub(1 + wr);

    float corr[2][2], f_[2][2];
    #pragma unroll
    for (int mt = 0; mt < 2; ++mt)
      #pragma unroll
      for (int h2 = 0; h2 < 2; ++h2) {
        int row = 32 * wr + 16 * mt + 8 * h2 + (lane >> 2);
        float2 rw[4];
        #pragma unroll
        for (int w2 = 0; w2 < 4; ++w2) rw[w2] = RED[w2 * 64 + row];
        float mnew = m_[mt][h2];
        #pragma unroll
        for (int w2 = 0; w2 < 4; ++w2) mnew = fmaxf(mnew, rw[w2].x);
        float c_ = ex2(m_[mt][h2] - mnew);
        float ls = l_[mt][h2] * c_;
        #pragma unroll
        for (int w2 = 0; w2 < 4; ++w2) ls += rw[w2].y * ex2(rw[w2].x - mnew);
        corr[mt][h2] = c_;
        f_[mt][h2]   = ex2(mw[mt][h2] - mnew);
        l_[mt][h2] = ls;
        m_[mt][h2] = mnew;
      }

    // ---- adaptive dropout + P -> smem -------------------------------------
    const float THR = 1e-8f;
    #pragma unroll
    for (int mt = 0; mt < 2; ++mt)
      #pragma unroll
      for (int h2 = 0; h2 < 2; ++h2) {
        int row = 32 * wr + 16 * mt + 8 * h2 + (lane >> 2);
        float fr = f_[mt][h2];
        float p0 = acc[mt][0][2*h2]   * fr;
        float p1 = acc[mt][0][2*h2+1] * fr;
        float p2 = acc[mt][1][2*h2]   * fr;
        float p3 = acc[mt][1][2*h2+1] * fr;
        unsigned ib = (gbase + (unsigned)row) * (unsigned)NKV
                    + (unsigned)(jt * BKV + 16 * wc + 2 * (lane & 3));
        if (__any_sync(0xffffffffu, p0 > THR)) {
          if (!keep_mask(ib)) p0 = 0.f;
        } else p0 = 0.f;
        if (__any_sync(0xffffffffu, p1 > THR)) {
          if (!keep_mask(ib + 1u)) p1 = 0.f;
        } else p1 = 0.f;
        if (__any_sync(0xffffffffu, p2 > THR)) {
          if (!keep_mask(ib + 8u)) p2 = 0.f;
        } else p2 = 0.f;
        if (__any_sync(0xffffffffu, p3 > THR)) {
          if (!keep_mask(ib + 9u)) p3 = 0.f;
        } else p3 = 0.f;
        int colB = (16 * wc + 2 * (lane & 3)) * 2;
        sts32(adr128(sb + SM_PH, row, colB),      packh(p0, p1));
        sts32(adr128(sb + SM_PH, row, colB + 16), packh(p2, p3));
      }
    barsub(1 + wr);

    // ---- O = O*corr + P V (V-hi only) -------------------------------------
    const uint32_t vb = sb + SM_VH0 + (uint32_t)((jt & 1) ? 16384u : 0u);
    const uint32_t bVA = vb + bVA_off, bVB = vb + bVB_off;
    #pragma unroll
    for (int mt = 0; mt < 2; ++mt)
      #pragma unroll
      for (int nt = 0; nt < 4; ++nt)
        #pragma unroll
        for (int e = 0; e < 4; ++e) OA[mt][nt][e] *= corr[mt][e >> 1];

    #pragma unroll
    for (int ks = 0; ks < 4; ++ks) {
      uint32_t ofsP = ((uint32_t)ks << 5) ^ cXA;
      uint32_t vof = (uint32_t)ks * 4096u;
      uint32_t ph0[4], ph1[4], vhA[4], vhB[4];
      ldsm4(ph0,  bP0 + ofsP);
      ldsm4(ph1,  bP1 + ofsP);
      ldsm4t(vhA, bVA + vof);
      ldsm4t(vhB, bVB + vof);
      mma_(OA[0][0], ph0, vhA[0], vhA[2]); mma_(OA[0][1], ph0, vhA[1], vhA[3]);
      mma_(OA[0][2], ph0, vhB[0], vhB[2]); mma_(OA[0][3], ph0, vhB[1], vhB[3]);
      mma_(OA[1][0], ph1, vhA[0], vhA[2]); mma_(OA[1][1], ph1, vhA[1], vhA[3]);
      mma_(OA[1][2], ph1, vhB[0], vhB[2]); mma_(OA[1][3], ph1, vhB[1], vhB[3]);
    }
  }

  // ---- epilogue ------------------------------------------------------------
  #pragma unroll
  for (int mt = 0; mt < 2; ++mt) {
    float inv0 = 1.0f / (l_[mt][0] * 0.9f);
    float inv1 = 1.0f / (l_[mt][1] * 0.9f);
    #pragma unroll
    for (int nt = 0; nt < 4; ++nt) {
      int col = 32 * wc + 8 * nt + 2 * (lane & 3);
      #pragma unroll
      for (int h2 = 0; h2 < 2; ++h2) {
        int row = 32 * wr + 16 * mt + 8 * h2 + (lane >> 2);
        float inv = h2 ? inv1 : inv0;
        float2 o;
        o.x = OA[mt][nt][2*h2]   * inv;
        o.y = OA[mt][nt][2*h2+1] * inv;
        *reinterpret_cast<float2*>(Og + (size_t)(gbase + row) * HD + col) = o;
      }
    }
  }
}

extern "C" void kernel_launch(void* const* d_in, const int* in_sizes, int n_in,
                              void* d_out, int out_size) {
  const float* Q = (const float*)d_in[0];
  const float* K = (const float*)d_in[1];
  const float* V = (const float*)d_in[2];
  float* O = (float*)d_out;
  (void)in_sizes; (void)n_in; (void)out_size;
  presplit_kernel<<<1024, 512>>>(Q, K, V);
  cudaFuncSetAttribute(Model_56358560858161_kernel,
                       cudaFuncAttributeMaxDynamicSharedMemorySize, (int)SM_TOT);
  Model_56358560858161_kernel<<<256, TB, SM_TOT>>>(O);
}

// round 17
// speedup vs baseline: 2.0649x; 1.0426x over previous
#include <cuda_runtime.h>
#include <cuda_fp16.h>
#include <cstdint>

// Round 17: FA2-style warp-local flash-attention. Warp = 16 q-rows x 32 kv
// cols; softmax warp-local (quad shuffles); P stays in registers (S C-fragment
// == AV A-fragment identity); zero mid-tile barriers beyond the 2 KV-buffer
// syncs. One end-of-kernel merge of the 2 kv-halves. Presplit f16 hi/lo in
// global, V-hi-only AV, V double-buffered, K prefetched post-S, log2 softmax,
// adaptive threefry (THR 1e-8).
// B=4, Q=4096, NKV=4096, H=128, scale=+sqrt(128)*log2(e) folded into Q.

#define TB  256
#define BQ  64
#define BKV 64
#define HD  128
#define NQ  4096
#define NKV 4096
#define NT  (NKV/BKV)
#define NW32 (4*4096*64)

__device__ uint32_t gQh[NW32], gQl[NW32], gKh[NW32], gKl[NW32], gVh[NW32];

#define SM_QH  0u
#define SM_QL  16384u
#define SM_KH  32768u
#define SM_KL  49152u
#define SM_VH0 65536u      // V hi, double-buffered (16 KB each)
#define SM_RED 98304u      // merge stats (64 x float2)
#define SM_OBUF 32768u     // merge O buffer overlays K region (32 KB)
#define SM_TOT 99328u

__device__ __forceinline__ uint32_t adr256(uint32_t base, int row, int colB) {
  uint32_t ch = ((uint32_t)colB >> 4) ^ ((uint32_t)row & 7u);
  return base + (uint32_t)row * 256u + ch * 16u + ((uint32_t)colB & 15u);
}
__device__ __forceinline__ void ldsm4(uint32_t* r, uint32_t a) {
  asm volatile("ldmatrix.sync.aligned.m8n8.x4.shared.b16 {%0,%1,%2,%3},[%4];"
               : "=r"(r[0]), "=r"(r[1]), "=r"(r[2]), "=r"(r[3]) : "r"(a));
}
__device__ __forceinline__ void ldsm4t(uint32_t* r, uint32_t a) {
  asm volatile("ldmatrix.sync.aligned.m8n8.x4.trans.shared.b16 {%0,%1,%2,%3},[%4];"
               : "=r"(r[0]), "=r"(r[1]), "=r"(r[2]), "=r"(r[3]) : "r"(a));
}
__device__ __forceinline__ void mma_(float* d, const uint32_t* a, uint32_t b0, uint32_t b1) {
  asm volatile(
    "mma.sync.aligned.m16n8k16.row.col.f32.f16.f16.f32 "
    "{%0,%1,%2,%3},{%4,%5,%6,%7},{%8,%9},{%0,%1,%2,%3};"
    : "+f"(d[0]), "+f"(d[1]), "+f"(d[2]), "+f"(d[3])
    : "r"(a[0]), "r"(a[1]), "r"(a[2]), "r"(a[3]), "r"(b0), "r"(b1));
}
__device__ __forceinline__ void cpa16(uint32_t d, const uint32_t* s) {
  asm volatile("cp.async.cg.shared.global [%0],[%1],16;" :: "r"(d), "l"(s));
}
__device__ __forceinline__ void cpa_commit() { asm volatile("cp.async.commit_group;"); }
__device__ __forceinline__ void cpa_wait0()  { asm volatile("cp.async.wait_group 0;"); }
__device__ __forceinline__ float ex2(float x) {
  float r; asm("ex2.approx.ftz.f32 %0, %1;" : "=f"(r) : "f"(x)); return r;
}
__device__ __forceinline__ void splith(float a, float b, uint32_t& hi, uint32_t& lo) {
  __half2 h = __floats2half2_rn(a, b);
  float2 hf = __half22float2(h);
  __half2 l = __floats2half2_rn(a - hf.x, b - hf.y);
  hi = *reinterpret_cast<uint32_t*>(&h);
  lo = *reinterpret_cast<uint32_t*>(&l);
}
__device__ __forceinline__ uint32_t packh(float a, float b) {
  __half2 h = __floats2half2_rn(a, b);
  return *reinterpret_cast<uint32_t*>(&h);
}

// JAX threefry2x32-20, key (0,42), partitionable: counter (0,i), bits=x0^x1
__device__ __forceinline__ unsigned keep_mask(unsigned idx) {
  const unsigned ks1 = 42u, ks2 = 0x1BD11BDAu ^ 42u;
  unsigned x0 = 0u, x1 = idx + ks1;
#define TFR(r) { x0 += x1; x1 = __funnelshift_l(x1, x1, (r)); x1 ^= x0; }
  TFR(13) TFR(15) TFR(26) TFR(6)
  x0 += ks1; x1 += ks2 + 1u;
  TFR(17) TFR(29) TFR(16) TFR(24)
  x0 += ks2; x1 += 2u;
  TFR(13) TFR(15) TFR(26) TFR(6)
  x1 += ks1 + 3u;
  TFR(17) TFR(29) TFR(16) TFR(24)
  x0 += ks1; x1 += ks2 + 4u;
  TFR(13) TFR(15) TFR(26) TFR(6)
  x0 += ks2; x1 += 5u;
#undef TFR
  return (((x0 ^ x1) >> 9) < 7549747u) ? 1u : 0u;
}

// ---- pre-split: fp32 -> f16 (Q scaled by sqrt(128)*log2(e); V hi only) -----
__global__ void __launch_bounds__(512)
presplit_kernel(const float* __restrict__ Q, const float* __restrict__ K,
                const float* __restrict__ V) {
  int i = blockIdx.x * 512 + threadIdx.x;
  const float SC2 = 16.32223106385f;   // sqrt(128) * log2(e)
  uint32_t h0, l0, h1, l1;
  float4 q = reinterpret_cast<const float4*>(Q)[i];
  splith(q.x * SC2, q.y * SC2, h0, l0);
  splith(q.z * SC2, q.w * SC2, h1, l1);
  gQh[2*i] = h0; gQh[2*i+1] = h1; gQl[2*i] = l0; gQl[2*i+1] = l1;
  float4 k = reinterpret_cast<const float4*>(K)[i];
  splith(k.x, k.y, h0, l0);
  splith(k.z, k.w, h1, l1);
  gKh[2*i] = h0; gKh[2*i+1] = h1; gKl[2*i] = l0; gKl[2*i+1] = l1;
  float4 v = reinterpret_cast<const float4*>(V)[i];
  gVh[2*i]   = packh(v.x, v.y);
  gVh[2*i+1] = packh(v.z, v.w);
}

__device__ __forceinline__ void issue_V(uint32_t vb, unsigned src, int tid) {
  #pragma unroll
  for (int it = 0; it < 4; ++it) {
    int c = tid + it * TB;
    int row = c >> 4, ch = c & 15;
    cpa16(adr256(vb, row, ch * 16), gVh + src + (unsigned)(row * 64 + ch * 4));
  }
}
__device__ __forceinline__ void issue_K(uint32_t sbase, unsigned src, int tid) {
  #pragma unroll
  for (int it = 0; it < 4; ++it) {
    int c = tid + it * TB;
    int row = c >> 4, ch = c & 15;
    unsigned o = src + (unsigned)(row * 64 + ch * 4);
    cpa16(adr256(sbase + SM_KH, row, ch * 16), gKh + o);
    cpa16(adr256(sbase + SM_KL, row, ch * 16), gKl + o);
  }
}

__global__ void __launch_bounds__(TB, 2)
Model_56358560858161_kernel(float* __restrict__ Og) {
  extern __shared__ __align__(1024) char smem[];
  const uint32_t sb = (uint32_t)__cvta_generic_to_shared(smem);

  const int tid  = threadIdx.x;
  const int lane = tid & 31, w = tid >> 5;
  const int wr = w & 3, wc = w >> 2;        // 4 row-groups x 2 kv-halves
  const int b  = blockIdx.x >> 6;
  const int q0 = (blockIdx.x & 63) * BQ;
  const unsigned gbase  = (unsigned)(b * NQ + q0);
  const unsigned qoff   = gbase * 64u;
  const unsigned kvbase = (unsigned)(b * NKV) * 64u;

  // ---- closed-form ldsm address bases --------------------------------------
  const int la7 = lane & 7, e8 = (lane >> 3) & 1, e16 = lane >> 4;
  const int rrA = la7 + e8 * 8;                       // A/B-frag row-in-16
  const uint32_t cXA = (uint32_t)((la7 ^ e16) << 4);  // swizzle XOR constant
  const uint32_t bQH  = sb + SM_QH + (uint32_t)(16 * wr + rrA) * 256u;
  const uint32_t bQL  = sb + SM_QL + (uint32_t)(16 * wr + rrA) * 256u;
  const uint32_t bKH0 = sb + SM_KH + (uint32_t)(32 * wc + rrA) * 256u;
  const uint32_t bKH1 = bKH0 + 4096u;
  const uint32_t bKL0 = sb + SM_KL + (uint32_t)(32 * wc + rrA) * 256u;
  const uint32_t bKL1 = bKL0 + 4096u;
  // V trans fragment: row = 32wc + 16s2 + la7 + 8e16 ; col chunk (2ng|e8)^la7
  const uint32_t bV_row = (uint32_t)(32 * wc + la7 + 8 * e16) * 256u;

  // ---- prologue: Q (both halves) + K(0) + V(0) ----------------------------
  #pragma unroll
  for (int it = 0; it < 4; ++it) {
    int c = tid + it * TB;
    int row = c >> 4, ch = c & 15;
    unsigned o = qoff + (unsigned)(row * 64 + ch * 4);
    cpa16(adr256(sb + SM_QH, row, ch * 16), gQh + o);
    cpa16(adr256(sb + SM_QL, row, ch * 16), gQl + o);
  }
  issue_K(sb, kvbase, tid);
  issue_V(sb + SM_VH0, kvbase, tid);
  cpa_commit();

  float m_[2], l_[2], OA[16][4];
  m_[0] = m_[1] = -1e30f; l_[0] = l_[1] = 0.f;
  #pragma unroll
  for (int nt = 0; nt < 16; ++nt)
    #pragma unroll
    for (int e = 0; e < 4; ++e) OA[nt][e] = 0.f;

  for (int jt = 0; jt < NT; ++jt) {
    cpa_wait0();
    __syncthreads();      // K(jt),V(jt) resident; all warps past AV(jt-1)

    if (jt + 1 < NT)
      issue_V(sb + SM_VH0 + (uint32_t)(((jt + 1) & 1) ? 16384u : 0u),
              kvbase + (unsigned)(jt + 1) * BKV * 64u, tid);
    cpa_commit();

    // ---- S = Q K^T : 16 rows x 32 kv cols per warp ------------------------
    float acc[4][4];
    #pragma unroll
    for (int nt = 0; nt < 4; ++nt)
      #pragma unroll
      for (int e = 0; e < 4; ++e) acc[nt][e] = 0.f;

    #pragma unroll
    for (int ks = 0; ks < 8; ++ks) {
      uint32_t ofs = ((uint32_t)ks << 5) ^ cXA;
      uint32_t ah[4], al[4], bh0[4], bh1[4], bl0[4], bl1[4];
      ldsm4(ah,  bQH  + ofs);
      ldsm4(al,  bQL  + ofs);
      ldsm4(bh0, bKH0 + ofs);
      ldsm4(bh1, bKH1 + ofs);
      ldsm4(bl0, bKL0 + ofs);
      ldsm4(bl1, bKL1 + ofs);
      mma_(acc[0], ah, bh0[0], bh0[2]); mma_(acc[1], ah, bh0[1], bh0[3]);
      mma_(acc[2], ah, bh1[0], bh1[2]); mma_(acc[3], ah, bh1[1], bh1[3]);
      mma_(acc[0], ah, bl0[0], bl0[2]); mma_(acc[1], ah, bl0[1], bl0[3]);
      mma_(acc[2], ah, bl1[0], bl1[2]); mma_(acc[3], ah, bl1[1], bl1[3]);
      mma_(acc[0], al, bh0[0], bh0[2]); mma_(acc[1], al, bh0[1], bh0[3]);
      mma_(acc[2], al, bh1[0], bh1[2]); mma_(acc[3], al, bh1[1], bh1[3]);
    }

    __syncthreads();      // all warps done reading K(jt)
    if (jt + 1 < NT)
      issue_K(sb, kvbase + (unsigned)(jt + 1) * BKV * 64u, tid);
    cpa_commit();         // K(jt+1) flies under softmax+AV

    // ---- warp-local softmax (log2 domain) + adaptive dropout --------------
    float corr[2];
    #pragma unroll
    for (int h2 = 0; h2 < 2; ++h2) {
      float mx = acc[0][2*h2];
      mx = fmaxf(mx, acc[0][2*h2+1]);
      #pragma unroll
      for (int nt = 1; nt < 4; ++nt)
        mx = fmaxf(mx, fmaxf(acc[nt][2*h2], acc[nt][2*h2+1]));
      mx = fmaxf(mx, __shfl_xor_sync(0xffffffffu, mx, 1));
      mx = fmaxf(mx, __shfl_xor_sync(0xffffffffu, mx, 2));
      float mnew = fmaxf(m_[h2], mx);
      corr[h2] = ex2(m_[h2] - mnew);
      float s = 0.f;
      #pragma unroll
      for (int nt = 0; nt < 4; ++nt)
        #pragma unroll
        for (int e = 0; e < 2; ++e) {
          float ex = ex2(acc[nt][2*h2+e] - mnew);
          acc[nt][2*h2+e] = ex;
          s += ex;
        }
      s += __shfl_xor_sync(0xffffffffu, s, 1);
      s += __shfl_xor_sync(0xffffffffu, s, 2);
      l_[h2] = l_[h2] * corr[h2] + s;
      m_[h2] = mnew;
    }

    const float THR = 1e-8f;
    #pragma unroll
    for (int h2 = 0; h2 < 2; ++h2) {
      int row = 16 * wr + (lane >> 2) + 8 * h2;
      unsigned ib = (gbase + (unsigned)row) * (unsigned)NKV
                  + (unsigned)(jt * BKV + 32 * wc + 2 * (lane & 3));
      #pragma unroll
      for (int nt = 0; nt < 4; ++nt) {
        float p0 = acc[nt][2*h2], p1 = acc[nt][2*h2+1];
        unsigned i0 = ib + (unsigned)(8 * nt);
        if (__any_sync(0xffffffffu, p0 > THR)) {
          if (!keep_mask(i0)) acc[nt][2*h2] = 0.f;
        } else acc[nt][2*h2] = 0.f;
        if (__any_sync(0xffffffffu, p1 > THR)) {
          if (!keep_mask(i0 + 1u)) acc[nt][2*h2+1] = 0.f;
        } else acc[nt][2*h2+1] = 0.f;
      }
    }

    // ---- P as AV A-fragments (C->A identity; registers only) --------------
    uint32_t ap[2][4];
    #pragma unroll
    for (int s2 = 0; s2 < 2; ++s2) {
      ap[s2][0] = packh(acc[2*s2][0],   acc[2*s2][1]);
      ap[s2][1] = packh(acc[2*s2][2],   acc[2*s2][3]);
      ap[s2][2] = packh(acc[2*s2+1][0], acc[2*s2+1][1]);
      ap[s2][3] = packh(acc[2*s2+1][2], acc[2*s2+1][3]);
    }

    // ---- O = O*corr + P V (V-hi only, kv slice 32wc..+32) -----------------
    const uint32_t vb = sb + SM_VH0 + (uint32_t)((jt & 1) ? 16384u : 0u)
                      + bV_row;
    #pragma unroll
    for (int nt = 0; nt < 16; ++nt)
      #pragma unroll
      for (int e = 0; e < 4; ++e) OA[nt][e] *= corr[e >> 1];

    #pragma unroll
    for (int s2 = 0; s2 < 2; ++s2) {
      uint32_t vks = vb + (uint32_t)s2 * 4096u;
      #pragma unroll
      for (int ng = 0; ng < 8; ++ng) {
        uint32_t vh[4];
        ldsm4t(vh, vks + (uint32_t)(((2 * ng) | e8) ^ la7) * 16u);
        mma_(OA[2*ng],   ap[s2], vh[0], vh[2]);
        mma_(OA[2*ng+1], ap[s2], vh[1], vh[3]);
      }
    }
  }

  // ---- end-of-kernel merge across the 2 kv-half warps ----------------------
  __syncthreads();   // everyone done with K/V smem; overlay Obuf/ML
  float*  Obuf = reinterpret_cast<float*>(smem + SM_OBUF);
  float2* ML   = reinterpret_cast<float2*>(smem + SM_RED);

  if (wc == 1) {
    #pragma unroll
    for (int h2 = 0; h2 < 2; ++h2) {
      int row = 16 * wr + (lane >> 2) + 8 * h2;
      if ((lane & 3) == 0) ML[row] = make_float2(m_[h2], l_[h2]);
    }
    #pragma unroll
    for (int nt = 0; nt < 16; ++nt) {
      int col = 8 * nt + 2 * (lane & 3);
      #pragma unroll
      for (int h2 = 0; h2 < 2; ++h2) {
        int row = 16 * wr + (lane >> 2) + 8 * h2;
        *reinterpret_cast<float2*>(&Obuf[row * HD + col]) =
            make_float2(OA[nt][2*h2], OA[nt][2*h2+1]);
      }
    }
  }
  __syncthreads();
  if (wc == 0) {
    float af[2], bf[2], inv[2];
    #pragma unroll
    for (int h2 = 0; h2 < 2; ++h2) {
      int row = 16 * wr + (lane >> 2) + 8 * h2;
      float2 ml = ML[row];
      float mm = fmaxf(m_[h2], ml.x);
      af[h2] = ex2(m_[h2] - mm);
      bf[h2] = ex2(ml.x - mm);
      float lt = l_[h2] * af[h2] + ml.y * bf[h2];
      inv[h2] = 1.0f / (lt * 0.9f);
    }
    #pragma unroll
    for (int nt = 0; nt < 16; ++nt) {
      int col = 8 * nt + 2 * (lane & 3);
      #pragma unroll
      for (int h2 = 0; h2 < 2; ++h2) {
        int row = 16 * wr + (lane >> 2) + 8 * h2;
        float2 ob = *reinterpret_cast<const float2*>(&Obuf[row * HD + col]);
        float2 o;
        o.x = (OA[nt][2*h2]   * af[h2] + ob.x * bf[h2]) * inv[h2];
        o.y = (OA[nt][2*h2+1] * af[h2] + ob.y * bf[h2]) * inv[h2];
        *reinterpret_cast<float2*>(Og + (size_t)(gbase + row) * HD + col) = o;
      }
    }
  }
}

extern "C" void kernel_launch(void* const* d_in, const int* in_sizes, int n_in,
                              void* d_out, int out_size) {
  const float* Q = (const float*)d_in[0];
  const float* K = (const float*)d_in[1];
  const float* V = (const float*)d_in[2];
  float* O = (float*)d_out;
  (void)in_sizes; (void)n_in; (void)out_size;
  presplit_kernel<<<1024, 512>>>(Q, K, V);
  cudaFuncSetAttribute(Model_56358560858161_kernel,
                       cudaFuncAttributeMaxDynamicSharedMemorySize, (int)SM_TOT);
  Model_56358560858161_kernel<<<256, TB, SM_TOT>>>(O);
}